// round 2
// baseline (speedup 1.0000x reference)
#include <cuda_runtime.h>
#include <cuda_bf16.h>
#include <cstddef>

#define BB   8
#define TT   1024
#define HH   128
#define BT   (BB*TT)

typedef unsigned long long ull;

__device__ __align__(16) float g_Q[BT*HH];
__device__ __align__(16) float g_K[BT*HH];
__device__ __align__(16) float g_V[BT*HH];
__device__ __align__(16) float g_A[BT*HH];
__device__ __align__(16) float g_F[BT*HH];
__device__ __align__(16) float g_X1[BT*HH];

__device__ __forceinline__ ull pk(float lo, float hi) {
    ull r; asm("mov.b64 %0,{%1,%2};" : "=l"(r) : "f"(lo), "f"(hi)); return r;
}
__device__ __forceinline__ void upk(ull v, float &lo, float &hi) {
    asm("mov.b64 {%0,%1},%2;" : "=f"(lo), "=f"(hi) : "l"(v));
}
__device__ __forceinline__ ull fma2(ull a, ull b, ull c) {
    ull d; asm("fma.rn.f32x2 %0,%1,%2,%3;" : "=l"(d) : "l"(a), "l"(b), "l"(c)); return d;
}
__device__ __forceinline__ ull mul2(ull a, ull b) {
    ull d; asm("mul.rn.f32x2 %0,%1,%2;" : "=l"(d) : "l"(a), "l"(b)); return d;
}
__device__ __forceinline__ void cp16(void* s, const void* g) {
    unsigned saddr = (unsigned)__cvta_generic_to_shared(s);
    asm volatile("cp.async.cg.shared.global [%0], [%1], 16;" :: "r"(saddr), "l"(g));
}

// MODE 0: identity   MODE 1: exp   MODE 2: exp * V
template<int MODE>
__device__ __forceinline__ void gemm_pass(const float* xs, int row0, int rgp, int cg,
                                          const float* __restrict__ W,
                                          const float* __restrict__ bias,
                                          const float* __restrict__ Vsrc,
                                          float* __restrict__ Y) {
    float acc[8][4];
    #pragma unroll
    for (int r = 0; r < 8; ++r) { acc[r][0]=0.f; acc[r][1]=0.f; acc[r][2]=0.f; acc[r][3]=0.f; }

    #pragma unroll 2
    for (int k4 = 0; k4 < 32; ++k4) {
        float4 xr[8];
        #pragma unroll
        for (int r = 0; r < 8; ++r)
            xr[r] = *(const float4*)&xs[(rgp*8 + r)*HH + k4*4];
        #pragma unroll
        for (int kk = 0; kk < 4; ++kk) {
            float4 w = *(const float4*)&W[(size_t)(k4*4 + kk)*HH + cg*4];
            #pragma unroll
            for (int r = 0; r < 8; ++r) {
                float xv = (kk==0) ? xr[r].x : (kk==1) ? xr[r].y : (kk==2) ? xr[r].z : xr[r].w;
                acc[r][0] = fmaf(xv, w.x, acc[r][0]);
                acc[r][1] = fmaf(xv, w.y, acc[r][1]);
                acc[r][2] = fmaf(xv, w.z, acc[r][2]);
                acc[r][3] = fmaf(xv, w.w, acc[r][3]);
            }
        }
    }
    float4 b4 = *(const float4*)&bias[cg*4];
    #pragma unroll
    for (int r = 0; r < 8; ++r) {
        size_t off = (size_t)(row0 + rgp*8 + r)*HH + cg*4;
        float4 o;
        o.x = acc[r][0] + b4.x; o.y = acc[r][1] + b4.y;
        o.z = acc[r][2] + b4.z; o.w = acc[r][3] + b4.w;
        if (MODE >= 1) { o.x = __expf(o.x); o.y = __expf(o.y); o.z = __expf(o.z); o.w = __expf(o.w); }
        if (MODE == 2) {
            float4 v = *(const float4*)&Vsrc[off];
            o.x *= v.x; o.y *= v.y; o.z *= v.z; o.w *= v.w;
        }
        *(float4*)&Y[off] = o;
    }
}

__global__ __launch_bounds__(256) void qkv_kernel(
    const float* __restrict__ X,
    const float* __restrict__ Wq, const float* __restrict__ bq,
    const float* __restrict__ Wk, const float* __restrict__ bk,
    const float* __restrict__ Wv, const float* __restrict__ bv) {
    __shared__ float xs[64*HH];
    const int tid = threadIdx.x;
    const int row0 = blockIdx.x * 64;
    for (int i = tid; i < 64*32; i += 256) {
        int r = i >> 5, c4 = i & 31;
        *(float4*)&xs[r*HH + c4*4] = *(const float4*)&X[(size_t)(row0 + r)*HH + c4*4];
    }
    __syncthreads();
    const int cg  = tid & 31;
    const int rgp = tid >> 5;
    gemm_pass<0>(xs, row0, rgp, cg, Wq, bq, nullptr, g_Q);
    gemm_pass<0>(xs, row0, rgp, cg, Wk, bk, nullptr, g_K);
    gemm_pass<0>(xs, row0, rgp, cg, Wv, bv, nullptr, g_V);
}

// use_x1: read layer input from g_X1 instead of the X pointer
__global__ __launch_bounds__(256) void gates_kernel(
    const float* __restrict__ Xp, int use_x1,
    const float* __restrict__ Wi, const float* __restrict__ bi,
    const float* __restrict__ Wf, const float* __restrict__ bf) {
    __shared__ float xs[64*HH];
    const int tid = threadIdx.x;
    const int row0 = blockIdx.x * 64;
    const float* X = use_x1 ? (const float*)g_X1 : Xp;
    for (int i = tid; i < 64*32; i += 256) {
        int r = i >> 5, c4 = i & 31;
        *(float4*)&xs[r*HH + c4*4] = *(const float4*)&X[(size_t)(row0 + r)*HH + c4*4];
    }
    __syncthreads();
    const int cg  = tid & 31;
    const int rgp = tid >> 5;
    gemm_pass<2>(xs, row0, rgp, cg, Wi, bi, g_V, g_A);
    gemm_pass<1>(xs, row0, rgp, cg, Wf, bf, nullptr, g_F);
}

__global__ __launch_bounds__(512, 1) void scan_kernel(
    const float* __restrict__ Wo, const float* __restrict__ bo,
    float* __restrict__ Xout_param) {
    const int b   = blockIdx.x;
    const int tid = threadIdx.x;
    const int j   = tid & 127;
    const int rg  = tid >> 7;
    const int r0  = rg << 5;
    const int pb  = r0 >> 2;

    __shared__ __align__(16) float4 stage[2][4][32];
    __shared__ __align__(16) float  hprev[128];
    __shared__ float part[8][128];

    float* Xout = Xout_param ? Xout_param : g_X1;

    const size_t base = (size_t)b * TT * HH;
    const float* Kb = g_K + base;
    const float* Qb = g_Q + base;
    const float* Ab = g_A + base;
    const float* Fb = g_F + base;

    ull w2[16];
    #pragma unroll
    for (int p = 0; p < 16; ++p)
        w2[p] = pk(Wo[(size_t)(r0 + 2*p)*HH + j], Wo[(size_t)(r0 + 2*p + 1)*HH + j]);
    const float bo_j = bo[j];

    ull C2[16];
    #pragma unroll
    for (int p = 0; p < 16; ++p) C2[p] = 0ull;

    if (tid < 128) hprev[tid] = 0.f;

    if (tid < 128) {
        int arr = tid >> 5, f4 = tid & 31;
        const float* src = (arr==0) ? Kb : (arr==1) ? Qb : (arr==2) ? Ab : Fb;
        cp16(&stage[0][arr][f4], src + f4*4);
    }
    asm volatile("cp.async.commit_group;" ::: "memory");

    for (int t = 0; t < TT; ++t) {
        const int buf = t & 1;
        if (tid < 128 && (t + 1) < TT) {
            int arr = tid >> 5, f4 = tid & 31;
            const float* src = (arr==0) ? Kb : (arr==1) ? Qb : (arr==2) ? Ab : Fb;
            cp16(&stage[buf^1][arr][f4], src + (size_t)(t+1)*HH + f4*4);
        }
        asm volatile("cp.async.commit_group;" ::: "memory");
        asm volatile("cp.async.wait_group 1;" ::: "memory");
        __syncthreads();

        const float kj = ((const float*)stage[buf][0])[j];
        const ull   kk = pk(kj, kj);
        const ulonglong2* qs = (const ulonglong2*)stage[buf][1];
        const ulonglong2* as = (const ulonglong2*)stage[buf][2];
        const ulonglong2* fs = (const ulonglong2*)stage[buf][3];
        ull pA = 0ull, pB = 0ull;
        #pragma unroll
        for (int p = 0; p < 8; ++p) {
            ulonglong2 q = qs[pb + p];
            ulonglong2 a = as[pb + p];
            ulonglong2 f = fs[pb + p];
            C2[2*p]     = fma2(f.x, C2[2*p],     mul2(a.x, kk));
            pA          = fma2(q.x, C2[2*p],     pA);
            C2[2*p + 1] = fma2(f.y, C2[2*p + 1], mul2(a.y, kk));
            pB          = fma2(q.y, C2[2*p + 1], pB);
        }
        {
            float l0, h0, l1, h1; upk(pA, l0, h0); upk(pB, l1, h1);
            part[rg][j] = (l0 + h0) + (l1 + h1);
        }
        {
            const ulonglong2* h2 = (const ulonglong2*)hprev;
            ull sA = 0ull, sB = 0ull;
            #pragma unroll
            for (int p = 0; p < 8; ++p) {
                ulonglong2 h = h2[pb + p];
                sA = fma2(h.x, w2[2*p],     sA);
                sB = fma2(h.y, w2[2*p + 1], sB);
            }
            float l0, h0, l1, h1; upk(sA, l0, h0); upk(sB, l1, h1);
            part[4 + rg][j] = (l0 + h0) + (l1 + h1);
        }
        __syncthreads();

        if (tid < 128) {
            float attn = part[0][j] + part[1][j] + part[2][j] + part[3][j];
            float og   = part[4][j] + part[5][j] + part[6][j] + part[7][j] + bo_j;
            float o    = 1.0f / (1.0f + __expf(-og));
            float h    = o * attn;
            hprev[j]   = h;
            Xout[base + (size_t)t*HH + j] = h;
        }
    }
}

extern "C" void kernel_launch(void* const* d_in, const int* in_sizes, int n_in,
                              void* d_out, int out_size) {
    const float* X  = (const float*)d_in[0];
    const float* Wq = (const float*)d_in[1];
    const float* bq = (const float*)d_in[2];
    const float* Wk = (const float*)d_in[3];
    const float* bk = (const float*)d_in[4];
    const float* Wv = (const float*)d_in[5];
    const float* bv = (const float*)d_in[6];
    const float* Wi = (const float*)d_in[7];
    const float* bi = (const float*)d_in[8];
    const float* Wf = (const float*)d_in[9];
    const float* bf = (const float*)d_in[10];
    const float* Wo = (const float*)d_in[11];
    const float* bo = (const float*)d_in[12];
    float* out = (float*)d_out;

    const int LW = HH*HH;
    const int LB = HH;

    qkv_kernel<<<BT/64, 256>>>(X, Wq, bq, Wk, bk, Wv, bv);

    gates_kernel<<<BT/64, 256>>>(X, 0, Wi + 0*LW, bi + 0*LB, Wf + 0*LW, bf + 0*LB);
    scan_kernel<<<BB, 512>>>(Wo + 0*LW, bo + 0*LB, nullptr);

    gates_kernel<<<BT/64, 256>>>(nullptr, 1, Wi + 1*LW, bi + 1*LB, Wf + 1*LW, bf + 1*LB);
    scan_kernel<<<BB, 512>>>(Wo + 1*LW, bo + 1*LB, out);
}

// round 6
// speedup vs baseline: 1.1949x; 1.1949x over previous
#include <cuda_runtime.h>
#include <cuda_bf16.h>
#include <cstddef>

#define BB   8
#define TT   1024
#define HH   128
#define BT   (BB*TT)

typedef unsigned long long ull;

// ---------------- device scratch ----------------
__device__ __align__(16) float g_Q[BT*HH];
__device__ __align__(16) float g_K[BT*HH];
__device__ __align__(16) float g_V[BT*HH];
__device__ __align__(16) float g_A[BT*HH];     // ig*v per layer
__device__ __align__(16) float g_F[BT*HH];     // fg per layer
__device__ __align__(16) float g_X1[BT*HH];    // layer-0 hidden output
__device__ __align__(16) float g_Attn[BT*HH];  // attn readout per layer

// ---------------- packed f32x2 helpers ----------------
__device__ __forceinline__ ull pk(float lo, float hi) {
    ull r; asm("mov.b64 %0,{%1,%2};" : "=l"(r) : "f"(lo), "f"(hi)); return r;
}
__device__ __forceinline__ void upk(ull v, float &lo, float &hi) {
    asm("mov.b64 {%0,%1},%2;" : "=f"(lo), "=f"(hi) : "l"(v));
}
__device__ __forceinline__ ull fma2(ull a, ull b, ull c) {
    ull d; asm("fma.rn.f32x2 %0,%1,%2,%3;" : "=l"(d) : "l"(a), "l"(b), "l"(c)); return d;
}
__device__ __forceinline__ ull mul2(ull a, ull b) {
    ull d; asm("mul.rn.f32x2 %0,%1,%2;" : "=l"(d) : "l"(a), "l"(b)); return d;
}
__device__ __forceinline__ ull add2(ull a, ull b) {
    ull d; asm("add.rn.f32x2 %0,%1,%2;" : "=l"(d) : "l"(a), "l"(b)); return d;
}
__device__ __forceinline__ void cp16(void* s, const void* g) {
    unsigned saddr = (unsigned)__cvta_generic_to_shared(s);
    asm volatile("cp.async.cg.shared.global [%0], [%1], 16;" :: "r"(saddr), "l"(g));
}
#define CP_COMMIT() asm volatile("cp.async.commit_group;" ::: "memory")
#define CP_WAIT2()  asm volatile("cp.async.wait_group 2;" ::: "memory")

// ---------------- GEMM pass: Y = act(xs @ W + b) ----------------
// MODE 0: identity   MODE 1: exp   MODE 2: exp * V
template<int MODE>
__device__ __forceinline__ void gemm_pass(const float* xs, int row0, int rgp, int cg,
                                          const float* __restrict__ W,
                                          const float* __restrict__ bias,
                                          const float* __restrict__ Vsrc,
                                          float* __restrict__ Y) {
    float acc[8][4];
    #pragma unroll
    for (int r = 0; r < 8; ++r) { acc[r][0]=0.f; acc[r][1]=0.f; acc[r][2]=0.f; acc[r][3]=0.f; }

    #pragma unroll 2
    for (int k4 = 0; k4 < 32; ++k4) {
        float4 xr[8];
        #pragma unroll
        for (int r = 0; r < 8; ++r)
            xr[r] = *(const float4*)&xs[(rgp*8 + r)*HH + k4*4];
        #pragma unroll
        for (int kk = 0; kk < 4; ++kk) {
            float4 w = *(const float4*)&W[(size_t)(k4*4 + kk)*HH + cg*4];
            #pragma unroll
            for (int r = 0; r < 8; ++r) {
                float xv = (kk==0) ? xr[r].x : (kk==1) ? xr[r].y : (kk==2) ? xr[r].z : xr[r].w;
                acc[r][0] = fmaf(xv, w.x, acc[r][0]);
                acc[r][1] = fmaf(xv, w.y, acc[r][1]);
                acc[r][2] = fmaf(xv, w.z, acc[r][2]);
                acc[r][3] = fmaf(xv, w.w, acc[r][3]);
            }
        }
    }
    float4 b4 = *(const float4*)&bias[cg*4];
    #pragma unroll
    for (int r = 0; r < 8; ++r) {
        size_t off = (size_t)(row0 + rgp*8 + r)*HH + cg*4;
        float4 o;
        o.x = acc[r][0] + b4.x; o.y = acc[r][1] + b4.y;
        o.z = acc[r][2] + b4.z; o.w = acc[r][3] + b4.w;
        if (MODE >= 1) { o.x = __expf(o.x); o.y = __expf(o.y); o.z = __expf(o.z); o.w = __expf(o.w); }
        if (MODE == 2) {
            float4 v = *(const float4*)&Vsrc[off];
            o.x *= v.x; o.y *= v.y; o.z *= v.z; o.w *= v.w;
        }
        *(float4*)&Y[off] = o;
    }
}

// Fused QKV + layer-0 gates. MODE2's g_V reads hit exactly the elements the
// same thread wrote in the V pass (same rgp/cg indexing), so no cross-thread dep.
__global__ __launch_bounds__(256) void qkvg_kernel(
    const float* __restrict__ X,
    const float* __restrict__ Wq, const float* __restrict__ bq,
    const float* __restrict__ Wk, const float* __restrict__ bk,
    const float* __restrict__ Wv, const float* __restrict__ bv,
    const float* __restrict__ Wi, const float* __restrict__ bi,
    const float* __restrict__ Wf, const float* __restrict__ bf) {
    __shared__ float xs[64*HH];
    const int tid = threadIdx.x;
    const int row0 = blockIdx.x * 64;
    for (int i = tid; i < 64*32; i += 256) {
        int r = i >> 5, c4 = i & 31;
        *(float4*)&xs[r*HH + c4*4] = *(const float4*)&X[(size_t)(row0 + r)*HH + c4*4];
    }
    __syncthreads();
    const int cg  = tid & 31;
    const int rgp = tid >> 5;
    gemm_pass<0>(xs, row0, rgp, cg, Wq, bq, nullptr, g_Q);
    gemm_pass<0>(xs, row0, rgp, cg, Wk, bk, nullptr, g_K);
    gemm_pass<0>(xs, row0, rgp, cg, Wv, bv, nullptr, g_V);
    gemm_pass<2>(xs, row0, rgp, cg, Wi, bi, g_V, g_A);
    gemm_pass<1>(xs, row0, rgp, cg, Wf, bf, nullptr, g_F);
}

// Layer-1 gates: reads layer input from g_X1.
__global__ __launch_bounds__(256) void gates_kernel(
    const float* __restrict__ Wi, const float* __restrict__ bi,
    const float* __restrict__ Wf, const float* __restrict__ bf) {
    __shared__ float xs[64*HH];
    const int tid = threadIdx.x;
    const int row0 = blockIdx.x * 64;
    const float* X = (const float*)g_X1;
    for (int i = tid; i < 64*32; i += 256) {
        int r = i >> 5, c4 = i & 31;
        *(float4*)&xs[r*HH + c4*4] = *(const float4*)&X[(size_t)(row0 + r)*HH + c4*4];
    }
    __syncthreads();
    const int cg  = tid & 31;
    const int rgp = tid >> 5;
    gemm_pass<2>(xs, row0, rgp, cg, Wi, bi, g_V, g_A);
    gemm_pass<1>(xs, row0, rgp, cg, Wf, bf, nullptr, g_F);
}

// ---------------- C-scan: 64 CTAs (b = blk>>3, cg = blk&7), 256 threads ----------------
// Thread (j16 = tid>>4, hg = tid&15): owns C[h][jg] for h in [hg*8, hg*8+8),
// jg = cg*16 + j16, as 4 packed f32x2 registers.
// Pipeline: 4 stage buffers, prefetch distance 3, wait_group 2, ONE barrier/step:
//   wait(G<=t) ; barrier ; issue prefetch t+3 ; compute.
// The barrier after the wait makes cp.async data visible to ALL threads (the R4 bug),
// and also separates last step's reads of the buffer being overwritten (WAR).
// attn reduce: 4x shfl.bfly over the 16 hg lanes, pipelined one step behind.
__global__ __launch_bounds__(256, 1) void cscan_kernel() {
    const int b   = blockIdx.x >> 3;
    const int cg  = blockIdx.x & 7;
    const int tid = threadIdx.x;
    const int j16 = tid >> 4;
    const int hg  = tid & 15;

    __shared__ __align__(16) float stage[4][4][HH];   // [buf][K,Q,A,F][128]

    const size_t base = (size_t)b * TT * HH;
    const float* Kb = g_K + base;
    const float* Qb = g_Q + base;
    const float* Ab = g_A + base;
    const float* Fb = g_F + base;

    ull C2[4];
    #pragma unroll
    for (int p = 0; p < 4; ++p) C2[p] = 0ull;

    const int arr = tid >> 5;        // 0..3 for tid<128
    const int f4  = tid & 31;
    const float* psrc = (arr==0) ? Kb : (arr==1) ? Qb : (arr==2) ? Ab : Fb;

    // pre-loop: prefetch targets 0,1,2 (one commit each; empty groups for tid>=128)
    #pragma unroll
    for (int d = 0; d < 3; ++d) {
        if (tid < 128) cp16(&stage[d][arr][f4*4], psrc + (size_t)d*HH + f4*4);
        CP_COMMIT();
    }

    const int jg = cg*16 + j16;
    const int b2 = hg*2;
    float ps_prev = 0.f;

    for (int t = 0; t < TT; ++t) {
        CP_WAIT2();        // committed targets 0..t+2 ; <=2 outstanding => target t complete
        __syncthreads();   // completion visible to all; prev reads of stage[(t+3)&3] done

        if (tid < 128 && (t + 3) < TT)
            cp16(&stage[(t+3)&3][arr][f4*4], psrc + (size_t)(t+3)*HH + f4*4);
        CP_COMMIT();

        // pipelined attn reduce for step t-1 (independent of this step's loads)
        if (t > 0) {
            float s = ps_prev;
            s += __shfl_xor_sync(0xffffffffu, s, 1);
            s += __shfl_xor_sync(0xffffffffu, s, 2);
            s += __shfl_xor_sync(0xffffffffu, s, 4);
            s += __shfl_xor_sync(0xffffffffu, s, 8);
            if (hg == 0) g_Attn[base + (size_t)(t-1)*HH + jg] = s;
        }

        const int buf = t & 3;
        const float kj = stage[buf][0][jg];
        const ull   kk = pk(kj, kj);
        const ulonglong2* qs = (const ulonglong2*)stage[buf][1];
        const ulonglong2* as = (const ulonglong2*)stage[buf][2];
        const ulonglong2* fs = (const ulonglong2*)stage[buf][3];
        ulonglong2 q0 = qs[b2], q1 = qs[b2+1];
        ulonglong2 a0 = as[b2], a1 = as[b2+1];
        ulonglong2 f0 = fs[b2], f1 = fs[b2+1];

        ull acc = 0ull;
        C2[0] = fma2(f0.x, C2[0], mul2(a0.x, kk));  acc = fma2(q0.x, C2[0], acc);
        C2[1] = fma2(f0.y, C2[1], mul2(a0.y, kk));  acc = fma2(q0.y, C2[1], acc);
        C2[2] = fma2(f1.x, C2[2], mul2(a1.x, kk));  acc = fma2(q1.x, C2[2], acc);
        C2[3] = fma2(f1.y, C2[3], mul2(a1.y, kk));  acc = fma2(q1.y, C2[3], acc);
        float lo, hi; upk(acc, lo, hi);
        ps_prev = lo + hi;
    }
    // tail: reduce + store t = TT-1
    {
        float s = ps_prev;
        s += __shfl_xor_sync(0xffffffffu, s, 1);
        s += __shfl_xor_sync(0xffffffffu, s, 2);
        s += __shfl_xor_sync(0xffffffffu, s, 4);
        s += __shfl_xor_sync(0xffffffffu, s, 8);
        if (hg == 0) g_Attn[base + (size_t)(TT-1)*HH + jg] = s;
    }
}

// ---------------- h recurrence: grid 8 (batch), 256 threads ----------------
// j = tid>>1, hg = tid&1: each thread sums 64 i's of Wo (register-resident);
// shfl.bfly(1) combines halves. 4 attn buffers, distance 3, wait_group 2,
// ONE barrier per step (after the wait -> fixes cp.async visibility).
__global__ __launch_bounds__(256, 1) void hrec_kernel(
    const float* __restrict__ Wo, const float* __restrict__ bo,
    float* __restrict__ Xout_param) {
    const int b   = blockIdx.x;
    const int tid = threadIdx.x;
    const int j   = tid >> 1;
    const int hg  = tid & 1;
    const int i0  = hg * 64;

    __shared__ __align__(16) float attnst[4][HH];
    __shared__ __align__(16) float hbuf[2][HH];

    float* Xout = Xout_param ? Xout_param : g_X1;
    const size_t base = (size_t)b * TT * HH;
    const float* Attnb = g_Attn + base;

    ull w2[32];
    #pragma unroll
    for (int p = 0; p < 32; ++p)
        w2[p] = pk(Wo[(size_t)(i0 + 2*p)*HH + j], Wo[(size_t)(i0 + 2*p + 1)*HH + j]);
    const float bo_j = bo[j];

    if (tid < 128) hbuf[0][tid] = 0.f;

    // pre-loop: prefetch attn targets 0,1,2
    #pragma unroll
    for (int d = 0; d < 3; ++d) {
        if (tid < 32) cp16(&attnst[d][tid*4], Attnb + (size_t)d*HH + tid*4);
        CP_COMMIT();
    }

    for (int t = 0; t < TT; ++t) {
        CP_WAIT2();
        __syncthreads();   // attnst[t&3] visible; hbuf write of step t-1 visible

        if (tid < 32 && (t + 3) < TT)
            cp16(&attnst[(t+3)&3][tid*4], Attnb + (size_t)(t+3)*HH + tid*4);
        CP_COMMIT();

        const int rb = t & 1;
        const ulonglong2* hb2 = (const ulonglong2*)hbuf[rb];

        ull s0 = 0ull, s1 = 0ull, s2 = 0ull, s3 = 0ull;
        #pragma unroll
        for (int p2 = 0; p2 < 8; ++p2) {
            ulonglong2 hh = hb2[hg*16 + p2];
            s0 = fma2(hh.x, w2[2*p2],     s0);
            s1 = fma2(hh.y, w2[2*p2 + 1], s1);
        }
        #pragma unroll
        for (int p2 = 8; p2 < 16; ++p2) {
            ulonglong2 hh = hb2[hg*16 + p2];
            s2 = fma2(hh.x, w2[2*p2],     s2);
            s3 = fma2(hh.y, w2[2*p2 + 1], s3);
        }
        ull st = add2(add2(s0, s1), add2(s2, s3));
        float lo, hi; upk(st, lo, hi);
        float zh = lo + hi;
        float zo = __shfl_xor_sync(0xffffffffu, zh, 1);
        float z  = zh + zo + bo_j;
        float o  = 1.0f / (1.0f + __expf(-z));
        float h  = o * attnst[t & 3][j];
        if (hg == 0) {
            hbuf[rb ^ 1][j] = h;                      // read next step after its barrier
            Xout[base + (size_t)t*HH + j] = h;
        }
    }
}

// ---------------- launch ----------------
extern "C" void kernel_launch(void* const* d_in, const int* in_sizes, int n_in,
                              void* d_out, int out_size) {
    const float* X  = (const float*)d_in[0];
    const float* Wq = (const float*)d_in[1];
    const float* bq = (const float*)d_in[2];
    const float* Wk = (const float*)d_in[3];
    const float* bk = (const float*)d_in[4];
    const float* Wv = (const float*)d_in[5];
    const float* bv = (const float*)d_in[6];
    const float* Wi = (const float*)d_in[7];
    const float* bi = (const float*)d_in[8];
    const float* Wf = (const float*)d_in[9];
    const float* bf = (const float*)d_in[10];
    const float* Wo = (const float*)d_in[11];
    const float* bo = (const float*)d_in[12];
    float* out = (float*)d_out;

    const int LW = HH*HH;
    const int LB = HH;

    qkvg_kernel<<<BT/64, 256>>>(X, Wq, bq, Wk, bk, Wv, bv,
                                Wi + 0*LW, bi + 0*LB, Wf + 0*LW, bf + 0*LB);
    cscan_kernel<<<BB*8, 256>>>();
    hrec_kernel<<<BB, 256>>>(Wo + 0*LW, bo + 0*LB, nullptr);   // -> g_X1

    gates_kernel<<<BT/64, 256>>>(Wi + 1*LW, bi + 1*LB, Wf + 1*LW, bf + 1*LB);
    cscan_kernel<<<BB*8, 256>>>();
    hrec_kernel<<<BB, 256>>>(Wo + 1*LW, bo + 1*LB, out);
}

// round 7
// speedup vs baseline: 1.3671x; 1.1441x over previous
#include <cuda_runtime.h>
#include <cuda_bf16.h>
#include <cstddef>

#define BB   8
#define TT   1024
#define HH   128
#define BT   (BB*TT)
#define NC   32          // chunks per (batch,layer)
#define SS   32          // chunk size
#define PAD  132         // smem row pitch (floats) to break 128-stride bank conflicts

typedef unsigned long long ull;

// ---------------- device scratch ----------------
__device__ __align__(16) float g_Q [BT*HH];
__device__ __align__(16) float g_K [BT*HH];
__device__ __align__(16) float g_V [BT*HH];
__device__ __align__(16) float g_A [BT*HH];      // a = exp(zi) * v   (per layer)
__device__ __align__(16) float g_F [BT*HH];      // zf LOGITS          (per layer)
__device__ __align__(16) float g_X1[BT*HH];      // layer-0 hidden output
__device__ __align__(16) float g_Attn[BT*HH];    // attn readout per layer
__device__ __align__(16) float g_Qt[BT*HH];      // q * exp(cum)
__device__ __align__(16) float g_At[BT*HH];      // a * exp(-cum)
__device__ __align__(16) float g_E [BB*NC*HH];   // exp(cum_S) per (b,c,h)
__device__ __align__(16) float g_U [BB*NC*HH*HH];  // per-chunk At^T @ K
__device__ __align__(16) float g_Cb[BB*NC*HH*HH];  // C at chunk start

// ---------------- packed f32x2 helpers ----------------
__device__ __forceinline__ ull pk(float lo, float hi) {
    ull r; asm("mov.b64 %0,{%1,%2};" : "=l"(r) : "f"(lo), "f"(hi)); return r;
}
__device__ __forceinline__ void upk(ull v, float &lo, float &hi) {
    asm("mov.b64 {%0,%1},%2;" : "=f"(lo), "=f"(hi) : "l"(v));
}
__device__ __forceinline__ ull fma2(ull a, ull b, ull c) {
    ull d; asm("fma.rn.f32x2 %0,%1,%2,%3;" : "=l"(d) : "l"(a), "l"(b), "l"(c)); return d;
}
__device__ __forceinline__ ull add2(ull a, ull b) {
    ull d; asm("add.rn.f32x2 %0,%1,%2;" : "=l"(d) : "l"(a), "l"(b)); return d;
}
__device__ __forceinline__ void cp16(void* s, const void* g) {
    unsigned saddr = (unsigned)__cvta_generic_to_shared(s);
    asm volatile("cp.async.cg.shared.global [%0], [%1], 16;" :: "r"(saddr), "l"(g));
}
#define CP_COMMIT() asm volatile("cp.async.commit_group;" ::: "memory")
#define CP_WAIT2()  asm volatile("cp.async.wait_group 2;" ::: "memory")

// ---------------- GEMM pass: Y = act(xs @ W + b) ----------------
// MODE 0: identity (used for Q,K,V and zf logits)   MODE 2: exp * V
template<int MODE>
__device__ __forceinline__ void gemm_pass(const float* xs, int row0, int rgp, int cg,
                                          const float* __restrict__ W,
                                          const float* __restrict__ bias,
                                          const float* __restrict__ Vsrc,
                                          float* __restrict__ Y) {
    float acc[8][4];
    #pragma unroll
    for (int r = 0; r < 8; ++r) { acc[r][0]=0.f; acc[r][1]=0.f; acc[r][2]=0.f; acc[r][3]=0.f; }

    #pragma unroll 2
    for (int k4 = 0; k4 < 32; ++k4) {
        float4 xr[8];
        #pragma unroll
        for (int r = 0; r < 8; ++r)
            xr[r] = *(const float4*)&xs[(rgp*8 + r)*HH + k4*4];
        #pragma unroll
        for (int kk = 0; kk < 4; ++kk) {
            float4 w = *(const float4*)&W[(size_t)(k4*4 + kk)*HH + cg*4];
            #pragma unroll
            for (int r = 0; r < 8; ++r) {
                float xv = (kk==0) ? xr[r].x : (kk==1) ? xr[r].y : (kk==2) ? xr[r].z : xr[r].w;
                acc[r][0] = fmaf(xv, w.x, acc[r][0]);
                acc[r][1] = fmaf(xv, w.y, acc[r][1]);
                acc[r][2] = fmaf(xv, w.z, acc[r][2]);
                acc[r][3] = fmaf(xv, w.w, acc[r][3]);
            }
        }
    }
    float4 b4 = *(const float4*)&bias[cg*4];
    #pragma unroll
    for (int r = 0; r < 8; ++r) {
        size_t off = (size_t)(row0 + rgp*8 + r)*HH + cg*4;
        float4 o;
        o.x = acc[r][0] + b4.x; o.y = acc[r][1] + b4.y;
        o.z = acc[r][2] + b4.z; o.w = acc[r][3] + b4.w;
        if (MODE == 2) {
            o.x = __expf(o.x); o.y = __expf(o.y); o.z = __expf(o.z); o.w = __expf(o.w);
            float4 v = *(const float4*)&Vsrc[off];
            o.x *= v.x; o.y *= v.y; o.z *= v.z; o.w *= v.w;
        }
        *(float4*)&Y[off] = o;
    }
}

// Fused QKV + layer-0 gate logits/a.
__global__ __launch_bounds__(256) void qkvg_kernel(
    const float* __restrict__ X,
    const float* __restrict__ Wq, const float* __restrict__ bq,
    const float* __restrict__ Wk, const float* __restrict__ bk,
    const float* __restrict__ Wv, const float* __restrict__ bv,
    const float* __restrict__ Wi, const float* __restrict__ bi,
    const float* __restrict__ Wf, const float* __restrict__ bf) {
    __shared__ float xs[64*HH];
    const int tid = threadIdx.x;
    const int row0 = blockIdx.x * 64;
    for (int i = tid; i < 64*32; i += 256) {
        int r = i >> 5, c4 = i & 31;
        *(float4*)&xs[r*HH + c4*4] = *(const float4*)&X[(size_t)(row0 + r)*HH + c4*4];
    }
    __syncthreads();
    const int cg  = tid & 31;
    const int rgp = tid >> 5;
    gemm_pass<0>(xs, row0, rgp, cg, Wq, bq, nullptr, g_Q);
    gemm_pass<0>(xs, row0, rgp, cg, Wk, bk, nullptr, g_K);
    gemm_pass<0>(xs, row0, rgp, cg, Wv, bv, nullptr, g_V);
    gemm_pass<2>(xs, row0, rgp, cg, Wi, bi, g_V, g_A);   // same-thread g_V reuse
    gemm_pass<0>(xs, row0, rgp, cg, Wf, bf, nullptr, g_F);  // zf LOGITS
}

// Layer-1 gates from g_X1.
__global__ __launch_bounds__(256) void gates_kernel(
    const float* __restrict__ Wi, const float* __restrict__ bi,
    const float* __restrict__ Wf, const float* __restrict__ bf) {
    __shared__ float xs[64*HH];
    const int tid = threadIdx.x;
    const int row0 = blockIdx.x * 64;
    const float* X = (const float*)g_X1;
    for (int i = tid; i < 64*32; i += 256) {
        int r = i >> 5, c4 = i & 31;
        *(float4*)&xs[r*HH + c4*4] = *(const float4*)&X[(size_t)(row0 + r)*HH + c4*4];
    }
    __syncthreads();
    const int cg  = tid & 31;
    const int rgp = tid >> 5;
    gemm_pass<2>(xs, row0, rgp, cg, Wi, bi, g_V, g_A);
    gemm_pass<0>(xs, row0, rgp, cg, Wf, bf, nullptr, g_F);  // logits
}

// ---------------- Phase A: per-chunk cumsum + Q~ / A~ / E ----------------
// grid 256 (b = blk>>5, c = blk&31), block 128 (h).
__global__ __launch_bounds__(128, 1) void prep_kernel() {
    const int b = blockIdx.x >> 5, c = blockIdx.x & 31;
    const int h = threadIdx.x;
    const size_t tb = ((size_t)b*TT + (size_t)c*SS) * HH;
    float cum = 0.f, e = 1.f;
    for (int s = 0; s < SS; ++s) {
        size_t idx = tb + (size_t)s*HH + h;
        cum += g_F[idx];
        e = __expf(cum);
        float ei = __expf(-cum);
        g_Qt[idx] = g_Q[idx] * e;
        g_At[idx] = g_A[idx] * ei;
    }
    g_E[(size_t)(b*NC + c)*HH + h] = e;
}

// ---------------- Phase B: per-chunk U = At^T K ; intra = mask(Qt At^T) K --------
// grid 256 (b,c), block 256.
__global__ __launch_bounds__(256, 1) void chunk_local_kernel() {
    const int b = blockIdx.x >> 5, c = blockIdx.x & 31;
    const int tid = threadIdx.x;
    const size_t tb = ((size_t)b*TT + (size_t)c*SS) * HH;

    __shared__ float tA[SS][PAD];
    __shared__ float tB[SS][PAD];
    __shared__ float Gs[SS][SS+1];

    // load At -> tA, K -> tB
    #pragma unroll
    for (int k = 0; k < 4; ++k) {
        int i = tid + k*256, s = i >> 5, c4 = i & 31;
        *(float4*)&tA[s][c4*4] = *(const float4*)&g_At[tb + (size_t)s*HH + c4*4];
        *(float4*)&tB[s][c4*4] = *(const float4*)&g_K [tb + (size_t)s*HH + c4*4];
    }
    __syncthreads();

    // U[h][j] = sum_s At[s][h] * K[s][j]
    {
        const int ty = tid >> 4, tx = tid & 15;
        const int h0 = ty*8, j0 = tx*8;
        float acc[8][8];
        #pragma unroll
        for (int r = 0; r < 8; ++r)
            #pragma unroll
            for (int q = 0; q < 8; ++q) acc[r][q] = 0.f;
        for (int s = 0; s < SS; ++s) {
            float av[8], kv[8];
            #pragma unroll
            for (int r = 0; r < 8; ++r) av[r] = tA[s][h0+r];
            #pragma unroll
            for (int q = 0; q < 8; ++q) kv[q] = tB[s][j0+q];
            #pragma unroll
            for (int r = 0; r < 8; ++r)
                #pragma unroll
                for (int q = 0; q < 8; ++q) acc[r][q] = fmaf(av[r], kv[q], acc[r][q]);
        }
        const size_t ub = (size_t)(b*NC + c) * (HH*HH);
        #pragma unroll
        for (int r = 0; r < 8; ++r) {
            *(float4*)&g_U[ub + (size_t)(h0+r)*HH + j0]     = make_float4(acc[r][0], acc[r][1], acc[r][2], acc[r][3]);
            *(float4*)&g_U[ub + (size_t)(h0+r)*HH + j0 + 4] = make_float4(acc[r][4], acc[r][5], acc[r][6], acc[r][7]);
        }
    }
    __syncthreads();   // done reading tB(K)

    // load Qt -> tB
    #pragma unroll
    for (int k = 0; k < 4; ++k) {
        int i = tid + k*256, s = i >> 5, c4 = i & 31;
        *(float4*)&tB[s][c4*4] = *(const float4*)&g_Qt[tb + (size_t)s*HH + c4*4];
    }
    __syncthreads();

    // G[t][s] = sum_h Qt[t][h]*At[s][h], causal mask s<=t
    #pragma unroll
    for (int i2 = 0; i2 < 4; ++i2) {
        int e = tid*4 + i2, t = e >> 5, s = e & 31;
        float d0=0.f, d1=0.f, d2=0.f, d3=0.f;
        for (int h = 0; h < HH; h += 4) {
            d0 = fmaf(tB[t][h+0], tA[s][h+0], d0);
            d1 = fmaf(tB[t][h+1], tA[s][h+1], d1);
            d2 = fmaf(tB[t][h+2], tA[s][h+2], d2);
            d3 = fmaf(tB[t][h+3], tA[s][h+3], d3);
        }
        Gs[t][s] = (s <= t) ? ((d0+d1)+(d2+d3)) : 0.f;
    }
    __syncthreads();   // Gs ready; tA(At) free

    // load K -> tA
    #pragma unroll
    for (int k = 0; k < 4; ++k) {
        int i = tid + k*256, s = i >> 5, c4 = i & 31;
        *(float4*)&tA[s][c4*4] = *(const float4*)&g_K[tb + (size_t)s*HH + c4*4];
    }
    __syncthreads();

    // intra[t][j] = sum_s Gs[t][s]*K[s][j]   (write g_Attn)
    {
        const int t = tid >> 3, j0 = (tid & 7) * 16;
        float acc[16];
        #pragma unroll
        for (int q = 0; q < 16; ++q) acc[q] = 0.f;
        for (int s = 0; s < SS; ++s) {
            float g = Gs[t][s];
            #pragma unroll
            for (int q = 0; q < 16; ++q) acc[q] = fmaf(g, tA[s][j0+q], acc[q]);
        }
        #pragma unroll
        for (int jj = 0; jj < 4; ++jj)
            *(float4*)&g_Attn[tb + (size_t)t*HH + j0 + jj*4] =
                make_float4(acc[jj*4], acc[jj*4+1], acc[jj*4+2], acc[jj*4+3]);
    }
}

// ---------------- Phase C: sequential chunk combine (register-resident C) -------
// grid 8 (b), block 512. Zero barriers: each thread owns 32 C elements privately.
__global__ __launch_bounds__(512, 1) void combine_kernel() {
    const int b = blockIdx.x, tid = threadIdx.x;
    float4 C[8];
    #pragma unroll
    for (int w = 0; w < 8; ++w) C[w] = make_float4(0.f, 0.f, 0.f, 0.f);
    int hI[8];
    #pragma unroll
    for (int w = 0; w < 8; ++w) hI[w] = w*16 + (tid >> 5);

    const float4* U4 = (const float4*)g_U;
    float4* Cb4 = (float4*)g_Cb;

    for (int c = 0; c < NC; ++c) {
        const size_t mb = (size_t)(b*NC + c) << 12;   // float4 units per matrix = 4096
        float4 u[8]; float e[8];
        #pragma unroll
        for (int w = 0; w < 8; ++w) {
            size_t fw = mb + (size_t)w*512 + tid;
            Cb4[fw] = C[w];                    // C at chunk start
            u[w] = __ldg(&U4[fw]);
            e[w] = __ldg(&g_E[(size_t)(b*NC + c)*HH + hI[w]]);
        }
        #pragma unroll
        for (int w = 0; w < 8; ++w) {
            C[w].x = e[w]*(C[w].x + u[w].x);
            C[w].y = e[w]*(C[w].y + u[w].y);
            C[w].z = e[w]*(C[w].z + u[w].z);
            C[w].w = e[w]*(C[w].w + u[w].w);
        }
    }
}

// ---------------- Phase D: inter = Qt @ Cb ; attn += inter ----------------
// grid 256 (b,c), block 256.
__global__ __launch_bounds__(256, 1) void chunk_inter_kernel() {
    const int b = blockIdx.x >> 5, c = blockIdx.x & 31;
    const int tid = threadIdx.x;
    const size_t tb = ((size_t)b*TT + (size_t)c*SS) * HH;
    const size_t cb = (size_t)(b*NC + c) * (HH*HH);

    __shared__ float tQ[SS][PAD];
    __shared__ float tC[SS][PAD];

    #pragma unroll
    for (int k = 0; k < 4; ++k) {
        int i = tid + k*256, s = i >> 5, c4 = i & 31;
        *(float4*)&tQ[s][c4*4] = *(const float4*)&g_Qt[tb + (size_t)s*HH + c4*4];
    }

    const int t = tid >> 3, j0 = (tid & 7) * 16;
    float acc[16];
    #pragma unroll
    for (int q = 0; q < 16; ++q) acc[q] = 0.f;

    for (int hb = 0; hb < 4; ++hb) {
        __syncthreads();   // prior slab consumed (also orders tQ load on hb=0)
        #pragma unroll
        for (int k = 0; k < 4; ++k) {
            int i = tid + k*256, s = i >> 5, c4 = i & 31;
            *(float4*)&tC[s][c4*4] = *(const float4*)&g_Cb[cb + (size_t)(hb*32 + s)*HH + c4*4];
        }
        __syncthreads();
        for (int hh = 0; hh < 32; ++hh) {
            float q = tQ[t][hb*32 + hh];
            #pragma unroll
            for (int qq = 0; qq < 16; ++qq) acc[qq] = fmaf(q, tC[hh][j0+qq], acc[qq]);
        }
    }

    #pragma unroll
    for (int jj = 0; jj < 4; ++jj) {
        float4 v = *(const float4*)&g_Attn[tb + (size_t)t*HH + j0 + jj*4];
        v.x += acc[jj*4]; v.y += acc[jj*4+1]; v.z += acc[jj*4+2]; v.w += acc[jj*4+3];
        *(float4*)&g_Attn[tb + (size_t)t*HH + j0 + jj*4] = v;
    }
}

// ---------------- h recurrence (unchanged from R6; proven correct) ----------------
__global__ __launch_bounds__(256, 1) void hrec_kernel(
    const float* __restrict__ Wo, const float* __restrict__ bo,
    float* __restrict__ Xout_param) {
    const int b   = blockIdx.x;
    const int tid = threadIdx.x;
    const int j   = tid >> 1;
    const int hg  = tid & 1;
    const int i0  = hg * 64;

    __shared__ __align__(16) float attnst[4][HH];
    __shared__ __align__(16) float hbuf[2][HH];

    float* Xout = Xout_param ? Xout_param : g_X1;
    const size_t base = (size_t)b * TT * HH;
    const float* Attnb = g_Attn + base;

    ull w2[32];
    #pragma unroll
    for (int p = 0; p < 32; ++p)
        w2[p] = pk(Wo[(size_t)(i0 + 2*p)*HH + j], Wo[(size_t)(i0 + 2*p + 1)*HH + j]);
    const float bo_j = bo[j];

    if (tid < 128) hbuf[0][tid] = 0.f;

    #pragma unroll
    for (int d = 0; d < 3; ++d) {
        if (tid < 32) cp16(&attnst[d][tid*4], Attnb + (size_t)d*HH + tid*4);
        CP_COMMIT();
    }

    for (int t = 0; t < TT; ++t) {
        CP_WAIT2();
        __syncthreads();

        if (tid < 32 && (t + 3) < TT)
            cp16(&attnst[(t+3)&3][tid*4], Attnb + (size_t)(t+3)*HH + tid*4);
        CP_COMMIT();

        const int rb = t & 1;
        const ulonglong2* hb2 = (const ulonglong2*)hbuf[rb];

        ull s0 = 0ull, s1 = 0ull, s2 = 0ull, s3 = 0ull;
        #pragma unroll
        for (int p2 = 0; p2 < 8; ++p2) {
            ulonglong2 hh = hb2[hg*16 + p2];
            s0 = fma2(hh.x, w2[2*p2],     s0);
            s1 = fma2(hh.y, w2[2*p2 + 1], s1);
        }
        #pragma unroll
        for (int p2 = 8; p2 < 16; ++p2) {
            ulonglong2 hh = hb2[hg*16 + p2];
            s2 = fma2(hh.x, w2[2*p2],     s2);
            s3 = fma2(hh.y, w2[2*p2 + 1], s3);
        }
        ull st = add2(add2(s0, s1), add2(s2, s3));
        float lo, hi; upk(st, lo, hi);
        float zh = lo + hi;
        float zo = __shfl_xor_sync(0xffffffffu, zh, 1);
        float z  = zh + zo + bo_j;
        float o  = 1.0f / (1.0f + __expf(-z));
        float h  = o * attnst[t & 3][j];
        if (hg == 0) {
            hbuf[rb ^ 1][j] = h;
            Xout[base + (size_t)t*HH + j] = h;
        }
    }
}

// ---------------- launch ----------------
extern "C" void kernel_launch(void* const* d_in, const int* in_sizes, int n_in,
                              void* d_out, int out_size) {
    const float* X  = (const float*)d_in[0];
    const float* Wq = (const float*)d_in[1];
    const float* bq = (const float*)d_in[2];
    const float* Wk = (const float*)d_in[3];
    const float* bk = (const float*)d_in[4];
    const float* Wv = (const float*)d_in[5];
    const float* bv = (const float*)d_in[6];
    const float* Wi = (const float*)d_in[7];
    const float* bi = (const float*)d_in[8];
    const float* Wf = (const float*)d_in[9];
    const float* bf = (const float*)d_in[10];
    const float* Wo = (const float*)d_in[11];
    const float* bo = (const float*)d_in[12];
    float* out = (float*)d_out;

    const int LW = HH*HH;
    const int LB = HH;

    qkvg_kernel<<<BT/64, 256>>>(X, Wq, bq, Wk, bk, Wv, bv,
                                Wi + 0*LW, bi + 0*LB, Wf + 0*LW, bf + 0*LB);
    prep_kernel<<<BB*NC, 128>>>();
    chunk_local_kernel<<<BB*NC, 256>>>();
    combine_kernel<<<BB, 512>>>();
    chunk_inter_kernel<<<BB*NC, 256>>>();
    hrec_kernel<<<BB, 256>>>(Wo + 0*LW, bo + 0*LB, nullptr);   // -> g_X1

    gates_kernel<<<BT/64, 256>>>(Wi + 1*LW, bi + 1*LB, Wf + 1*LW, bf + 1*LB);
    prep_kernel<<<BB*NC, 128>>>();
    chunk_local_kernel<<<BB*NC, 256>>>();
    combine_kernel<<<BB, 512>>>();
    chunk_inter_kernel<<<BB*NC, 256>>>();
    hrec_kernel<<<BB, 256>>>(Wo + 1*LW, bo + 1*LB, out);
}

// round 8
// speedup vs baseline: 1.5239x; 1.1147x over previous
#include <cuda_runtime.h>
#include <cuda_bf16.h>
#include <cstddef>

#define BB   8
#define TT   1024
#define HH   128
#define BT   (BB*TT)
#define NC   32          // chunks per (batch,layer)
#define SS   32          // chunk size
#define PAD  132         // smem row pitch (floats) to break 128-stride bank conflicts

typedef unsigned long long ull;

// ---------------- device scratch ----------------
__device__ __align__(16) float g_Q [BT*HH];
__device__ __align__(16) float g_K [BT*HH];
__device__ __align__(16) float g_V [BT*HH];
__device__ __align__(16) float g_A [BT*HH];      // a = exp(zi) * v   (per layer)
__device__ __align__(16) float g_F [BT*HH];      // zf LOGITS          (per layer)
__device__ __align__(16) float g_X1[BT*HH];      // layer-0 hidden output
__device__ __align__(16) float g_Attn[BT*HH];    // attn readout per layer
__device__ __align__(16) float g_Qt[BT*HH];      // q * exp(cum)
__device__ __align__(16) float g_At[BT*HH];      // a * exp(-cum)
__device__ __align__(16) float g_E [BB*NC*HH];   // exp(cum_S) per (b,c,h)
__device__ __align__(16) float g_U [BB*NC*HH*HH];  // per-chunk At^T @ K
__device__ __align__(16) float g_Cb[BB*NC*HH*HH];  // C at chunk start

// ---------------- packed f32x2 helpers ----------------
__device__ __forceinline__ ull pk(float lo, float hi) {
    ull r; asm("mov.b64 %0,{%1,%2};" : "=l"(r) : "f"(lo), "f"(hi)); return r;
}
__device__ __forceinline__ void upk(ull v, float &lo, float &hi) {
    asm("mov.b64 {%0,%1},%2;" : "=f"(lo), "=f"(hi) : "l"(v));
}
__device__ __forceinline__ ull fma2(ull a, ull b, ull c) {
    ull d; asm("fma.rn.f32x2 %0,%1,%2,%3;" : "=l"(d) : "l"(a), "l"(b), "l"(c)); return d;
}
__device__ __forceinline__ ull add2(ull a, ull b) {
    ull d; asm("add.rn.f32x2 %0,%1,%2;" : "=l"(d) : "l"(a), "l"(b)); return d;
}

// ---------------- GEMM pass: Y = act(xs @ W + b) ----------------
// MODE 0: identity   MODE 2: exp * V
template<int MODE>
__device__ __forceinline__ void gemm_pass(const float* xs, int row0, int rgp, int cg,
                                          const float* __restrict__ W,
                                          const float* __restrict__ bias,
                                          const float* __restrict__ Vsrc,
                                          float* __restrict__ Y) {
    float acc[8][4];
    #pragma unroll
    for (int r = 0; r < 8; ++r) { acc[r][0]=0.f; acc[r][1]=0.f; acc[r][2]=0.f; acc[r][3]=0.f; }

    #pragma unroll 2
    for (int k4 = 0; k4 < 32; ++k4) {
        float4 xr[8];
        #pragma unroll
        for (int r = 0; r < 8; ++r)
            xr[r] = *(const float4*)&xs[(rgp*8 + r)*HH + k4*4];
        #pragma unroll
        for (int kk = 0; kk < 4; ++kk) {
            float4 w = *(const float4*)&W[(size_t)(k4*4 + kk)*HH + cg*4];
            #pragma unroll
            for (int r = 0; r < 8; ++r) {
                float xv = (kk==0) ? xr[r].x : (kk==1) ? xr[r].y : (kk==2) ? xr[r].z : xr[r].w;
                acc[r][0] = fmaf(xv, w.x, acc[r][0]);
                acc[r][1] = fmaf(xv, w.y, acc[r][1]);
                acc[r][2] = fmaf(xv, w.z, acc[r][2]);
                acc[r][3] = fmaf(xv, w.w, acc[r][3]);
            }
        }
    }
    float4 b4 = *(const float4*)&bias[cg*4];
    #pragma unroll
    for (int r = 0; r < 8; ++r) {
        size_t off = (size_t)(row0 + rgp*8 + r)*HH + cg*4;
        float4 o;
        o.x = acc[r][0] + b4.x; o.y = acc[r][1] + b4.y;
        o.z = acc[r][2] + b4.z; o.w = acc[r][3] + b4.w;
        if (MODE == 2) {
            o.x = __expf(o.x); o.y = __expf(o.y); o.z = __expf(o.z); o.w = __expf(o.w);
            float4 v = *(const float4*)&Vsrc[off];
            o.x *= v.x; o.y *= v.y; o.z *= v.z; o.w *= v.w;
        }
        *(float4*)&Y[off] = o;
    }
}

// Fused QKV + layer-0 gate a/logits.
__global__ __launch_bounds__(256) void qkvg_kernel(
    const float* __restrict__ X,
    const float* __restrict__ Wq, const float* __restrict__ bq,
    const float* __restrict__ Wk, const float* __restrict__ bk,
    const float* __restrict__ Wv, const float* __restrict__ bv,
    const float* __restrict__ Wi, const float* __restrict__ bi,
    const float* __restrict__ Wf, const float* __restrict__ bf) {
    __shared__ float xs[64*HH];
    const int tid = threadIdx.x;
    const int row0 = blockIdx.x * 64;
    for (int i = tid; i < 64*32; i += 256) {
        int r = i >> 5, c4 = i & 31;
        *(float4*)&xs[r*HH + c4*4] = *(const float4*)&X[(size_t)(row0 + r)*HH + c4*4];
    }
    __syncthreads();
    const int cg  = tid & 31;
    const int rgp = tid >> 5;
    gemm_pass<0>(xs, row0, rgp, cg, Wq, bq, nullptr, g_Q);
    gemm_pass<0>(xs, row0, rgp, cg, Wk, bk, nullptr, g_K);
    gemm_pass<0>(xs, row0, rgp, cg, Wv, bv, nullptr, g_V);
    gemm_pass<2>(xs, row0, rgp, cg, Wi, bi, g_V, g_A);   // same-thread g_V reuse
    gemm_pass<0>(xs, row0, rgp, cg, Wf, bf, nullptr, g_F);  // zf LOGITS
}

// Layer-1 gates from g_X1.
__global__ __launch_bounds__(256) void gates_kernel(
    const float* __restrict__ Wi, const float* __restrict__ bi,
    const float* __restrict__ Wf, const float* __restrict__ bf) {
    __shared__ float xs[64*HH];
    const int tid = threadIdx.x;
    const int row0 = blockIdx.x * 64;
    const float* X = (const float*)g_X1;
    for (int i = tid; i < 64*32; i += 256) {
        int r = i >> 5, c4 = i & 31;
        *(float4*)&xs[r*HH + c4*4] = *(const float4*)&X[(size_t)(row0 + r)*HH + c4*4];
    }
    __syncthreads();
    const int cg  = tid & 31;
    const int rgp = tid >> 5;
    gemm_pass<2>(xs, row0, rgp, cg, Wi, bi, g_V, g_A);
    gemm_pass<0>(xs, row0, rgp, cg, Wf, bf, nullptr, g_F);  // logits
}

// ---------------- Phase A: per-chunk cumsum + Q~ / A~ / E ----------------
__global__ __launch_bounds__(128, 1) void prep_kernel() {
    const int b = blockIdx.x >> 5, c = blockIdx.x & 31;
    const int h = threadIdx.x;
    const size_t tb = ((size_t)b*TT + (size_t)c*SS) * HH;
    float cum = 0.f, e = 1.f;
    for (int s = 0; s < SS; ++s) {
        size_t idx = tb + (size_t)s*HH + h;
        cum += g_F[idx];
        e = __expf(cum);
        float ei = __expf(-cum);
        g_Qt[idx] = g_Q[idx] * e;
        g_At[idx] = g_A[idx] * ei;
    }
    g_E[(size_t)(b*NC + c)*HH + h] = e;
}

// ---------------- Phase B: per-chunk U = At^T K ; intra = mask(Qt At^T) K --------
__global__ __launch_bounds__(256, 1) void chunk_local_kernel() {
    const int b = blockIdx.x >> 5, c = blockIdx.x & 31;
    const int tid = threadIdx.x;
    const size_t tb = ((size_t)b*TT + (size_t)c*SS) * HH;

    __shared__ float tA[SS][PAD];
    __shared__ float tB[SS][PAD];
    __shared__ float Gs[SS][SS+1];

    #pragma unroll
    for (int k = 0; k < 4; ++k) {
        int i = tid + k*256, s = i >> 5, c4 = i & 31;
        *(float4*)&tA[s][c4*4] = *(const float4*)&g_At[tb + (size_t)s*HH + c4*4];
        *(float4*)&tB[s][c4*4] = *(const float4*)&g_K [tb + (size_t)s*HH + c4*4];
    }
    __syncthreads();

    // U[h][j] = sum_s At[s][h] * K[s][j]
    {
        const int ty = tid >> 4, tx = tid & 15;
        const int h0 = ty*8, j0 = tx*8;
        float acc[8][8];
        #pragma unroll
        for (int r = 0; r < 8; ++r)
            #pragma unroll
            for (int q = 0; q < 8; ++q) acc[r][q] = 0.f;
        for (int s = 0; s < SS; ++s) {
            float av[8], kv[8];
            #pragma unroll
            for (int r = 0; r < 8; ++r) av[r] = tA[s][h0+r];
            #pragma unroll
            for (int q = 0; q < 8; ++q) kv[q] = tB[s][j0+q];
            #pragma unroll
            for (int r = 0; r < 8; ++r)
                #pragma unroll
                for (int q = 0; q < 8; ++q) acc[r][q] = fmaf(av[r], kv[q], acc[r][q]);
        }
        const size_t ub = (size_t)(b*NC + c) * (HH*HH);
        #pragma unroll
        for (int r = 0; r < 8; ++r) {
            *(float4*)&g_U[ub + (size_t)(h0+r)*HH + j0]     = make_float4(acc[r][0], acc[r][1], acc[r][2], acc[r][3]);
            *(float4*)&g_U[ub + (size_t)(h0+r)*HH + j0 + 4] = make_float4(acc[r][4], acc[r][5], acc[r][6], acc[r][7]);
        }
    }
    __syncthreads();

    // load Qt -> tB
    #pragma unroll
    for (int k = 0; k < 4; ++k) {
        int i = tid + k*256, s = i >> 5, c4 = i & 31;
        *(float4*)&tB[s][c4*4] = *(const float4*)&g_Qt[tb + (size_t)s*HH + c4*4];
    }
    __syncthreads();

    // G[t][s] = sum_h Qt[t][h]*At[s][h], causal mask s<=t
    #pragma unroll
    for (int i2 = 0; i2 < 4; ++i2) {
        int e = tid*4 + i2, t = e >> 5, s = e & 31;
        float d0=0.f, d1=0.f, d2=0.f, d3=0.f;
        for (int h = 0; h < HH; h += 4) {
            d0 = fmaf(tB[t][h+0], tA[s][h+0], d0);
            d1 = fmaf(tB[t][h+1], tA[s][h+1], d1);
            d2 = fmaf(tB[t][h+2], tA[s][h+2], d2);
            d3 = fmaf(tB[t][h+3], tA[s][h+3], d3);
        }
        Gs[t][s] = (s <= t) ? ((d0+d1)+(d2+d3)) : 0.f;
    }
    __syncthreads();

    // load K -> tA
    #pragma unroll
    for (int k = 0; k < 4; ++k) {
        int i = tid + k*256, s = i >> 5, c4 = i & 31;
        *(float4*)&tA[s][c4*4] = *(const float4*)&g_K[tb + (size_t)s*HH + c4*4];
    }
    __syncthreads();

    // intra[t][j] = sum_s Gs[t][s]*K[s][j]
    {
        const int t = tid >> 3, j0 = (tid & 7) * 16;
        float acc[16];
        #pragma unroll
        for (int q = 0; q < 16; ++q) acc[q] = 0.f;
        for (int s = 0; s < SS; ++s) {
            float g = Gs[t][s];
            #pragma unroll
            for (int q = 0; q < 16; ++q) acc[q] = fmaf(g, tA[s][j0+q], acc[q]);
        }
        #pragma unroll
        for (int jj = 0; jj < 4; ++jj)
            *(float4*)&g_Attn[tb + (size_t)t*HH + j0 + jj*4] =
                make_float4(acc[jj*4], acc[jj*4+1], acc[jj*4+2], acc[jj*4+3]);
    }
}

// ---------------- Phase C: chunk combine, 128 CTAs (b, 8-row h slice) -----------
// Each thread owns one float4 (row r = hs*8 + tid>>5, cols (tid&31)*4) of C.
// Serial over 32 chunks with U/E prefetch distance 1. No barriers.
__global__ __launch_bounds__(256, 1) void combine_kernel() {
    const int b  = blockIdx.x >> 4;
    const int hs = blockIdx.x & 15;
    const int tid = threadIdx.x;
    const int r  = hs*8 + (tid >> 5);     // global h row 0..127
    const int c4 = tid & 31;              // float4 column

    const float4* U4 = (const float4*)g_U;
    float4* Cb4 = (float4*)g_Cb;
    const int elem = r*32 + c4;           // float4 offset within a 128x128 matrix

    float4 C = make_float4(0.f, 0.f, 0.f, 0.f);
    size_t m0 = ((size_t)(b*NC) << 12) + elem;
    float4 u = __ldg(&U4[m0]);
    float  e = __ldg(&g_E[(size_t)(b*NC)*HH + r]);

    for (int c = 0; c < NC; ++c) {
        float4 un; float en;
        if (c + 1 < NC) {
            size_t mn = ((size_t)(b*NC + c + 1) << 12) + elem;
            un = __ldg(&U4[mn]);
            en = __ldg(&g_E[(size_t)(b*NC + c + 1)*HH + r]);
        } else { un = u; en = e; }
        Cb4[((size_t)(b*NC + c) << 12) + elem] = C;
        C.x = e*(C.x + u.x); C.y = e*(C.y + u.y);
        C.z = e*(C.z + u.z); C.w = e*(C.w + u.w);
        u = un; e = en;
    }
}

// ---------------- Phase D: inter = Qt @ Cb ; attn += inter ----------------
__global__ __launch_bounds__(256, 1) void chunk_inter_kernel() {
    const int b = blockIdx.x >> 5, c = blockIdx.x & 31;
    const int tid = threadIdx.x;
    const size_t tb = ((size_t)b*TT + (size_t)c*SS) * HH;
    const size_t cb = (size_t)(b*NC + c) * (HH*HH);

    __shared__ float tQ[SS][PAD];
    __shared__ float tC[SS][PAD];

    #pragma unroll
    for (int k = 0; k < 4; ++k) {
        int i = tid + k*256, s = i >> 5, c4 = i & 31;
        *(float4*)&tQ[s][c4*4] = *(const float4*)&g_Qt[tb + (size_t)s*HH + c4*4];
    }

    const int t = tid >> 3, j0 = (tid & 7) * 16;
    float acc[16];
    #pragma unroll
    for (int q = 0; q < 16; ++q) acc[q] = 0.f;

    for (int hb = 0; hb < 4; ++hb) {
        __syncthreads();
        #pragma unroll
        for (int k = 0; k < 4; ++k) {
            int i = tid + k*256, s = i >> 5, c4 = i & 31;
            *(float4*)&tC[s][c4*4] = *(const float4*)&g_Cb[cb + (size_t)(hb*32 + s)*HH + c4*4];
        }
        __syncthreads();
        for (int hh = 0; hh < 32; ++hh) {
            float q = tQ[t][hb*32 + hh];
            #pragma unroll
            for (int qq = 0; qq < 16; ++qq) acc[qq] = fmaf(q, tC[hh][j0+qq], acc[qq]);
        }
    }

    #pragma unroll
    for (int jj = 0; jj < 4; ++jj) {
        float4 v = *(const float4*)&g_Attn[tb + (size_t)t*HH + j0 + jj*4];
        v.x += acc[jj*4]; v.y += acc[jj*4+1]; v.z += acc[jj*4+2]; v.w += acc[jj*4+3];
        *(float4*)&g_Attn[tb + (size_t)t*HH + j0 + jj*4] = v;
    }
}

// ---------------- h recurrence: LDG register ring, 1 barrier/step ----------------
// j = tid>>1, hg = tid&1. attn prefetched via direct LDG, distance 8 (static ring
// indices via unroll-by-8). No cp.async, no attn smem.
__global__ __launch_bounds__(256, 1) void hrec_kernel(
    const float* __restrict__ Wo, const float* __restrict__ bo,
    float* __restrict__ Xout_param) {
    const int b   = blockIdx.x;
    const int tid = threadIdx.x;
    const int j   = tid >> 1;
    const int hg  = tid & 1;
    const int i0  = hg * 64;

    __shared__ __align__(16) float hbuf[2][HH];

    float* Xout = Xout_param ? Xout_param : g_X1;
    const size_t base = (size_t)b * TT * HH;
    const float* Attnb = g_Attn + base;

    ull w2[32];
    #pragma unroll
    for (int p = 0; p < 32; ++p)
        w2[p] = pk(Wo[(size_t)(i0 + 2*p)*HH + j], Wo[(size_t)(i0 + 2*p + 1)*HH + j]);
    const float bo_j = bo[j];

    if (tid < 128) hbuf[0][tid] = 0.f;

    float ring[8];
    #pragma unroll
    for (int u = 0; u < 8; ++u)
        ring[u] = (hg == 0) ? __ldg(Attnb + (size_t)u*HH + j) : 0.f;

    for (int tb = 0; tb < TT; tb += 8) {
        #pragma unroll
        for (int u = 0; u < 8; ++u) {
            const int t = tb + u;
            __syncthreads();   // hbuf[t&1] (written at t-1) visible to all

            const ulonglong2* hb2 = (const ulonglong2*)hbuf[t & 1];
            ull s0 = 0ull, s1 = 0ull, s2 = 0ull, s3 = 0ull;
            #pragma unroll
            for (int p2 = 0; p2 < 8; ++p2) {
                ulonglong2 hh = hb2[hg*16 + p2];
                s0 = fma2(hh.x, w2[2*p2],     s0);
                s1 = fma2(hh.y, w2[2*p2 + 1], s1);
            }
            #pragma unroll
            for (int p2 = 8; p2 < 16; ++p2) {
                ulonglong2 hh = hb2[hg*16 + p2];
                s2 = fma2(hh.x, w2[2*p2],     s2);
                s3 = fma2(hh.y, w2[2*p2 + 1], s3);
            }
            ull st = add2(add2(s0, s1), add2(s2, s3));
            float lo, hi; upk(st, lo, hi);
            float zh = lo + hi;
            float zo = __shfl_xor_sync(0xffffffffu, zh, 1);
            float z  = zh + zo + bo_j;
            float o  = 1.0f / (1.0f + __expf(-z));
            if (hg == 0) {
                float h = o * ring[u];
                hbuf[(t & 1) ^ 1][j] = h;
                Xout[base + (size_t)t*HH + j] = h;
                if (t + 8 < TT)
                    ring[u] = __ldg(Attnb + (size_t)(t + 8)*HH + j);
            }
        }
    }
}

// ---------------- launch ----------------
extern "C" void kernel_launch(void* const* d_in, const int* in_sizes, int n_in,
                              void* d_out, int out_size) {
    const float* X  = (const float*)d_in[0];
    const float* Wq = (const float*)d_in[1];
    const float* bq = (const float*)d_in[2];
    const float* Wk = (const float*)d_in[3];
    const float* bk = (const float*)d_in[4];
    const float* Wv = (const float*)d_in[5];
    const float* bv = (const float*)d_in[6];
    const float* Wi = (const float*)d_in[7];
    const float* bi = (const float*)d_in[8];
    const float* Wf = (const float*)d_in[9];
    const float* bf = (const float*)d_in[10];
    const float* Wo = (const float*)d_in[11];
    const float* bo = (const float*)d_in[12];
    float* out = (float*)d_out;

    const int LW = HH*HH;
    const int LB = HH;

    qkvg_kernel<<<BT/64, 256>>>(X, Wq, bq, Wk, bk, Wv, bv,
                                Wi + 0*LW, bi + 0*LB, Wf + 0*LW, bf + 0*LB);
    prep_kernel<<<BB*NC, 128>>>();
    chunk_local_kernel<<<BB*NC, 256>>>();
    combine_kernel<<<BB*16, 256>>>();
    chunk_inter_kernel<<<BB*NC, 256>>>();
    hrec_kernel<<<BB, 256>>>(Wo + 0*LW, bo + 0*LB, nullptr);   // -> g_X1

    gates_kernel<<<BT/64, 256>>>(Wi + 1*LW, bi + 1*LB, Wf + 1*LW, bf + 1*LB);
    prep_kernel<<<BB*NC, 128>>>();
    chunk_local_kernel<<<BB*NC, 256>>>();
    combine_kernel<<<BB*16, 256>>>();
    chunk_inter_kernel<<<BB*NC, 256>>>();
    hrec_kernel<<<BB, 256>>>(Wo + 1*LW, bo + 1*LB, out);
}

// round 9
// speedup vs baseline: 1.7310x; 1.1359x over previous
#include <cuda_runtime.h>
#include <cuda_bf16.h>
#include <cstddef>

#define BB   8
#define TT   1024
#define HH   128
#define BT   (BB*TT)
#define NC   32          // chunks per (batch,layer)
#define SS   32          // chunk size
#define PAD  132         // smem row pitch (floats) to break 128-stride bank conflicts

typedef unsigned long long ull;

// ---------------- device scratch ----------------
__device__ __align__(16) float g_Q [BT*HH];
__device__ __align__(16) float g_K [BT*HH];
__device__ __align__(16) float g_V [BT*HH];
__device__ __align__(16) float g_A [BT*HH];      // a = exp(zi) * v   (per layer)
__device__ __align__(16) float g_X1[BT*HH];      // layer-0 hidden output
__device__ __align__(16) float g_Attn[BT*HH];    // attn readout per layer
__device__ __align__(16) float g_Qt[BT*HH];      // q * exp(cum)
__device__ __align__(16) float g_At[BT*HH];      // a * exp(-cum)
__device__ __align__(16) float g_E [BB*NC*HH];   // exp(cum_S) per (b,c,h)
__device__ __align__(16) float g_U [BB*NC*HH*HH];  // per-chunk At^T @ K
__device__ __align__(16) float g_Cb[BB*NC*HH*HH];  // C at chunk start

// ---------------- packed f32x2 helpers ----------------
__device__ __forceinline__ ull pk(float lo, float hi) {
    ull r; asm("mov.b64 %0,{%1,%2};" : "=l"(r) : "f"(lo), "f"(hi)); return r;
}
__device__ __forceinline__ void upk(ull v, float &lo, float &hi) {
    asm("mov.b64 {%0,%1},%2;" : "=f"(lo), "=f"(hi) : "l"(v));
}
__device__ __forceinline__ ull fma2(ull a, ull b, ull c) {
    ull d; asm("fma.rn.f32x2 %0,%1,%2,%3;" : "=l"(d) : "l"(a), "l"(b), "l"(c)); return d;
}
__device__ __forceinline__ ull add2(ull a, ull b) {
    ull d; asm("add.rn.f32x2 %0,%1,%2;" : "=l"(d) : "l"(a), "l"(b)); return d;
}

// ---------------- GEMM accumulation (no epilogue) ----------------
__device__ __forceinline__ void gemm_acc(const float* xs, int rgp, int cg,
                                         const float* __restrict__ W,
                                         float acc[8][4]) {
    #pragma unroll
    for (int r = 0; r < 8; ++r) { acc[r][0]=0.f; acc[r][1]=0.f; acc[r][2]=0.f; acc[r][3]=0.f; }
    #pragma unroll 2
    for (int k4 = 0; k4 < 32; ++k4) {
        float4 xr[8];
        #pragma unroll
        for (int r = 0; r < 8; ++r)
            xr[r] = *(const float4*)&xs[(rgp*8 + r)*HH + k4*4];
        #pragma unroll
        for (int kk = 0; kk < 4; ++kk) {
            float4 w = *(const float4*)&W[(size_t)(k4*4 + kk)*HH + cg*4];
            #pragma unroll
            for (int r = 0; r < 8; ++r) {
                float xv = (kk==0) ? xr[r].x : (kk==1) ? xr[r].y : (kk==2) ? xr[r].z : xr[r].w;
                acc[r][0] = fmaf(xv, w.x, acc[r][0]);
                acc[r][1] = fmaf(xv, w.y, acc[r][1]);
                acc[r][2] = fmaf(xv, w.z, acc[r][2]);
                acc[r][3] = fmaf(xv, w.w, acc[r][3]);
            }
        }
    }
}

// MODE 0: identity -> global   MODE 2: exp * V -> global
template<int MODE>
__device__ __forceinline__ void gemm_pass(const float* xs, int row0, int rgp, int cg,
                                          const float* __restrict__ W,
                                          const float* __restrict__ bias,
                                          const float* __restrict__ Vsrc,
                                          float* __restrict__ Y) {
    float acc[8][4];
    gemm_acc(xs, rgp, cg, W, acc);
    float4 b4 = *(const float4*)&bias[cg*4];
    #pragma unroll
    for (int r = 0; r < 8; ++r) {
        size_t off = (size_t)(row0 + rgp*8 + r)*HH + cg*4;
        float4 o;
        o.x = acc[r][0] + b4.x; o.y = acc[r][1] + b4.y;
        o.z = acc[r][2] + b4.z; o.w = acc[r][3] + b4.w;
        if (MODE == 2) {
            o.x = __expf(o.x); o.y = __expf(o.y); o.z = __expf(o.z); o.w = __expf(o.w);
            float4 v = *(const float4*)&Vsrc[off];
            o.x *= v.x; o.y *= v.y; o.z *= v.z; o.w *= v.w;
        }
        *(float4*)&Y[off] = o;
    }
}

// F-logit pass into smem (reuses xs after a barrier) + fused per-chunk cumsum:
// writes g_Qt, g_At, g_E directly. Block = 64 rows of one batch = 2 chunks.
__device__ __forceinline__ void f_cumsum_tail(float* xs, int row0, int rgp, int cg, int tid,
                                              const float* __restrict__ Wf,
                                              const float* __restrict__ bf) {
    float acc[8][4];
    gemm_acc(xs, rgp, cg, Wf, acc);
    __syncthreads();                      // all reads of xs (X tile) done
    float4 b4 = *(const float4*)&bf[cg*4];
    #pragma unroll
    for (int r = 0; r < 8; ++r) {
        float4 o;
        o.x = acc[r][0] + b4.x; o.y = acc[r][1] + b4.y;
        o.z = acc[r][2] + b4.z; o.w = acc[r][3] + b4.w;
        *(float4*)&xs[(rgp*8 + r)*HH + cg*4] = o;      // F logits -> smem
    }
    __syncthreads();                      // F tile visible (also fences this block's
                                          // earlier global writes of g_Q / g_A)
    // cumsum: thread owns (chunk ch = tid>>7, column h = tid&127)
    const int ch = tid >> 7;
    const int h  = tid & 127;
    const int b  = row0 / TT;
    const int c  = ((row0 % TT) / SS) + ch;
    const size_t tbg = ((size_t)row0 + (size_t)ch*SS) * HH;
    float cum = 0.f, e = 1.f;
    #pragma unroll 4
    for (int s = 0; s < SS; ++s) {
        cum += xs[(ch*SS + s)*HH + h];
        e = __expf(cum);
        float ei = __expf(-cum);
        size_t idx = tbg + (size_t)s*HH + h;
        g_Qt[idx] = g_Q[idx] * e;
        g_At[idx] = g_A[idx] * ei;
    }
    g_E[(size_t)(b*NC + c)*HH + h] = e;
}

// Fused QKV + layer-0 gates + cumsum/prep.
__global__ __launch_bounds__(256) void qkvg_kernel(
    const float* __restrict__ X,
    const float* __restrict__ Wq, const float* __restrict__ bq,
    const float* __restrict__ Wk, const float* __restrict__ bk,
    const float* __restrict__ Wv, const float* __restrict__ bv,
    const float* __restrict__ Wi, const float* __restrict__ bi,
    const float* __restrict__ Wf, const float* __restrict__ bf) {
    __shared__ float xs[64*HH];
    const int tid = threadIdx.x;
    const int row0 = blockIdx.x * 64;
    for (int i = tid; i < 64*32; i += 256) {
        int r = i >> 5, c4 = i & 31;
        *(float4*)&xs[r*HH + c4*4] = *(const float4*)&X[(size_t)(row0 + r)*HH + c4*4];
    }
    __syncthreads();
    const int cg  = tid & 31;
    const int rgp = tid >> 5;
    gemm_pass<0>(xs, row0, rgp, cg, Wq, bq, nullptr, g_Q);
    gemm_pass<0>(xs, row0, rgp, cg, Wk, bk, nullptr, g_K);
    gemm_pass<0>(xs, row0, rgp, cg, Wv, bv, nullptr, g_V);
    gemm_pass<2>(xs, row0, rgp, cg, Wi, bi, g_V, g_A);   // same-thread g_V reuse
    f_cumsum_tail(xs, row0, rgp, cg, tid, Wf, bf);
}

// Layer-1 gates from g_X1 (+ fused cumsum/prep).
__global__ __launch_bounds__(256) void gates_kernel(
    const float* __restrict__ Wi, const float* __restrict__ bi,
    const float* __restrict__ Wf, const float* __restrict__ bf) {
    __shared__ float xs[64*HH];
    const int tid = threadIdx.x;
    const int row0 = blockIdx.x * 64;
    const float* X = (const float*)g_X1;
    for (int i = tid; i < 64*32; i += 256) {
        int r = i >> 5, c4 = i & 31;
        *(float4*)&xs[r*HH + c4*4] = *(const float4*)&X[(size_t)(row0 + r)*HH + c4*4];
    }
    __syncthreads();
    const int cg  = tid & 31;
    const int rgp = tid >> 5;
    gemm_pass<2>(xs, row0, rgp, cg, Wi, bi, g_V, g_A);
    f_cumsum_tail(xs, row0, rgp, cg, tid, Wf, bf);
}

// ---------------- Phase B: per-chunk U = At^T K ; intra = mask(Qt At^T) K --------
__global__ __launch_bounds__(256, 1) void chunk_local_kernel() {
    const int b = blockIdx.x >> 5, c = blockIdx.x & 31;
    const int tid = threadIdx.x;
    const size_t tb = ((size_t)b*TT + (size_t)c*SS) * HH;

    __shared__ float tA[SS][PAD];
    __shared__ float tB[SS][PAD];
    __shared__ float Gs[SS][SS+1];

    #pragma unroll
    for (int k = 0; k < 4; ++k) {
        int i = tid + k*256, s = i >> 5, c4 = i & 31;
        *(float4*)&tA[s][c4*4] = *(const float4*)&g_At[tb + (size_t)s*HH + c4*4];
        *(float4*)&tB[s][c4*4] = *(const float4*)&g_K [tb + (size_t)s*HH + c4*4];
    }
    __syncthreads();

    // U[h][j] = sum_s At[s][h] * K[s][j]
    {
        const int ty = tid >> 4, tx = tid & 15;
        const int h0 = ty*8, j0 = tx*8;
        float acc[8][8];
        #pragma unroll
        for (int r = 0; r < 8; ++r)
            #pragma unroll
            for (int q = 0; q < 8; ++q) acc[r][q] = 0.f;
        for (int s = 0; s < SS; ++s) {
            float av[8], kv[8];
            #pragma unroll
            for (int r = 0; r < 8; ++r) av[r] = tA[s][h0+r];
            #pragma unroll
            for (int q = 0; q < 8; ++q) kv[q] = tB[s][j0+q];
            #pragma unroll
            for (int r = 0; r < 8; ++r)
                #pragma unroll
                for (int q = 0; q < 8; ++q) acc[r][q] = fmaf(av[r], kv[q], acc[r][q]);
        }
        const size_t ub = (size_t)(b*NC + c) * (HH*HH);
        #pragma unroll
        for (int r = 0; r < 8; ++r) {
            *(float4*)&g_U[ub + (size_t)(h0+r)*HH + j0]     = make_float4(acc[r][0], acc[r][1], acc[r][2], acc[r][3]);
            *(float4*)&g_U[ub + (size_t)(h0+r)*HH + j0 + 4] = make_float4(acc[r][4], acc[r][5], acc[r][6], acc[r][7]);
        }
    }
    __syncthreads();

    // load Qt -> tB
    #pragma unroll
    for (int k = 0; k < 4; ++k) {
        int i = tid + k*256, s = i >> 5, c4 = i & 31;
        *(float4*)&tB[s][c4*4] = *(const float4*)&g_Qt[tb + (size_t)s*HH + c4*4];
    }
    __syncthreads();

    // G[t][s] = sum_h Qt[t][h]*At[s][h], causal mask s<=t
    #pragma unroll
    for (int i2 = 0; i2 < 4; ++i2) {
        int e = tid*4 + i2, t = e >> 5, s = e & 31;
        float d0=0.f, d1=0.f, d2=0.f, d3=0.f;
        for (int h = 0; h < HH; h += 4) {
            d0 = fmaf(tB[t][h+0], tA[s][h+0], d0);
            d1 = fmaf(tB[t][h+1], tA[s][h+1], d1);
            d2 = fmaf(tB[t][h+2], tA[s][h+2], d2);
            d3 = fmaf(tB[t][h+3], tA[s][h+3], d3);
        }
        Gs[t][s] = (s <= t) ? ((d0+d1)+(d2+d3)) : 0.f;
    }
    __syncthreads();

    // load K -> tA
    #pragma unroll
    for (int k = 0; k < 4; ++k) {
        int i = tid + k*256, s = i >> 5, c4 = i & 31;
        *(float4*)&tA[s][c4*4] = *(const float4*)&g_K[tb + (size_t)s*HH + c4*4];
    }
    __syncthreads();

    // intra[t][j] = sum_s Gs[t][s]*K[s][j]
    {
        const int t = tid >> 3, j0 = (tid & 7) * 16;
        float acc[16];
        #pragma unroll
        for (int q = 0; q < 16; ++q) acc[q] = 0.f;
        for (int s = 0; s < SS; ++s) {
            float g = Gs[t][s];
            #pragma unroll
            for (int q = 0; q < 16; ++q) acc[q] = fmaf(g, tA[s][j0+q], acc[q]);
        }
        #pragma unroll
        for (int jj = 0; jj < 4; ++jj)
            *(float4*)&g_Attn[tb + (size_t)t*HH + j0 + jj*4] =
                make_float4(acc[jj*4], acc[jj*4+1], acc[jj*4+2], acc[jj*4+3]);
    }
}

// ---------------- Phase C: chunk combine, 128 CTAs ----------------
__global__ __launch_bounds__(256, 1) void combine_kernel() {
    const int b  = blockIdx.x >> 4;
    const int hs = blockIdx.x & 15;
    const int tid = threadIdx.x;
    const int r  = hs*8 + (tid >> 5);
    const int c4 = tid & 31;

    const float4* U4 = (const float4*)g_U;
    float4* Cb4 = (float4*)g_Cb;
    const int elem = r*32 + c4;

    float4 C = make_float4(0.f, 0.f, 0.f, 0.f);
    size_t m0 = ((size_t)(b*NC) << 12) + elem;
    float4 u = __ldg(&U4[m0]);
    float  e = __ldg(&g_E[(size_t)(b*NC)*HH + r]);

    for (int c = 0; c < NC; ++c) {
        float4 un; float en;
        if (c + 1 < NC) {
            size_t mn = ((size_t)(b*NC + c + 1) << 12) + elem;
            un = __ldg(&U4[mn]);
            en = __ldg(&g_E[(size_t)(b*NC + c + 1)*HH + r]);
        } else { un = u; en = e; }
        Cb4[((size_t)(b*NC + c) << 12) + elem] = C;
        C.x = e*(C.x + u.x); C.y = e*(C.y + u.y);
        C.z = e*(C.z + u.z); C.w = e*(C.w + u.w);
        u = un; e = en;
    }
}

// ---------------- Phase D: inter = Qt @ Cb ; attn += inter ----------------
__global__ __launch_bounds__(256, 1) void chunk_inter_kernel() {
    const int b = blockIdx.x >> 5, c = blockIdx.x & 31;
    const int tid = threadIdx.x;
    const size_t tb = ((size_t)b*TT + (size_t)c*SS) * HH;
    const size_t cb = (size_t)(b*NC + c) * (HH*HH);

    __shared__ float tQ[SS][PAD];
    __shared__ float tC[SS][PAD];

    #pragma unroll
    for (int k = 0; k < 4; ++k) {
        int i = tid + k*256, s = i >> 5, c4 = i & 31;
        *(float4*)&tQ[s][c4*4] = *(const float4*)&g_Qt[tb + (size_t)s*HH + c4*4];
    }

    const int t = tid >> 3, j0 = (tid & 7) * 16;
    float acc[16];
    #pragma unroll
    for (int q = 0; q < 16; ++q) acc[q] = 0.f;

    for (int hb = 0; hb < 4; ++hb) {
        __syncthreads();
        #pragma unroll
        for (int k = 0; k < 4; ++k) {
            int i = tid + k*256, s = i >> 5, c4 = i & 31;
            *(float4*)&tC[s][c4*4] = *(const float4*)&g_Cb[cb + (size_t)(hb*32 + s)*HH + c4*4];
        }
        __syncthreads();
        for (int hh = 0; hh < 32; ++hh) {
            float q = tQ[t][hb*32 + hh];
            #pragma unroll
            for (int qq = 0; qq < 16; ++qq) acc[qq] = fmaf(q, tC[hh][j0+qq], acc[qq]);
        }
    }

    #pragma unroll
    for (int jj = 0; jj < 4; ++jj) {
        float4 v = *(const float4*)&g_Attn[tb + (size_t)t*HH + j0 + jj*4];
        v.x += acc[jj*4]; v.y += acc[jj*4+1]; v.z += acc[jj*4+2]; v.w += acc[jj*4+3];
        *(float4*)&g_Attn[tb + (size_t)t*HH + j0 + jj*4] = v;
    }
}

// ---------------- h recurrence: branch-free, log2-folded sigmoid ----------------
// j = tid>>1, hg = tid&1. Both hg lanes redundantly compute/store h (same-address
// STS/STG within a warp coalesce) -> NO divergent branch in the loop.
// Wo, bo pre-scaled by -log2(e): matvec gives zl = -z*log2e; sigma = rcp(1+ex2(zl)).
__global__ __launch_bounds__(256, 1) void hrec_kernel(
    const float* __restrict__ Wo, const float* __restrict__ bo,
    float* __restrict__ Xout_param) {
    const int b   = blockIdx.x;
    const int tid = threadIdx.x;
    const int j   = tid >> 1;
    const int hg  = tid & 1;
    const int i0  = hg * 64;
    const float NL2E = -1.44269504088896f;

    __shared__ __align__(16) float hbuf[2][HH];

    float* Xout = Xout_param ? Xout_param : g_X1;
    const size_t base = (size_t)b * TT * HH;
    const float* Attnb = g_Attn + base;

    ull w2[32];
    #pragma unroll
    for (int p = 0; p < 32; ++p)
        w2[p] = pk(NL2E * Wo[(size_t)(i0 + 2*p)*HH + j],
                   NL2E * Wo[(size_t)(i0 + 2*p + 1)*HH + j]);
    const float bo2 = NL2E * bo[j];

    if (tid < 128) hbuf[0][tid] = 0.f;

    float ring[8];
    #pragma unroll
    for (int u = 0; u < 8; ++u)
        ring[u] = __ldg(Attnb + (size_t)u*HH + j);     // both lanes (broadcast)

    for (int tb = 0; tb < TT; tb += 8) {
        #pragma unroll
        for (int u = 0; u < 8; ++u) {
            const int t = tb + u;
            __syncthreads();   // hbuf[t&1] (written at t-1) visible

            const ulonglong2* hb2 = (const ulonglong2*)hbuf[t & 1];
            ull s[8];
            #pragma unroll
            for (int q = 0; q < 8; ++q) s[q] = 0ull;
            #pragma unroll
            for (int q = 0; q < 16; ++q) {
                ulonglong2 hh = hb2[hg*16 + q];
                s[(2*q)   & 7] = fma2(hh.x, w2[2*q],     s[(2*q)   & 7]);
                s[(2*q+1) & 7] = fma2(hh.y, w2[2*q + 1], s[(2*q+1) & 7]);
            }
            ull t0 = add2(s[0], s[1]), t1 = add2(s[2], s[3]);
            ull t2 = add2(s[4], s[5]), t3 = add2(s[6], s[7]);
            ull st = add2(add2(t0, t1), add2(t2, t3));
            float lo, hi; upk(st, lo, hi);
            float zh = lo + hi;
            float zo = __shfl_xor_sync(0xffffffffu, zh, 1);
            float zl = zh + zo + bo2;                     // = -z * log2(e)
            float ex; asm("ex2.approx.f32 %0, %1;" : "=f"(ex) : "f"(zl));   // e^-z
            float den = 1.0f + ex;
            float o;  asm("rcp.approx.f32 %0, %1;" : "=f"(o) : "f"(den));
            float h = o * ring[u];
            hbuf[(t & 1) ^ 1][j] = h;                     // both lanes, same value
            Xout[base + (size_t)t*HH + j] = h;            // both lanes, same value
            if (t + 8 < TT)
                ring[u] = __ldg(Attnb + (size_t)(t + 8)*HH + j);
        }
    }
}

// ---------------- launch ----------------
extern "C" void kernel_launch(void* const* d_in, const int* in_sizes, int n_in,
                              void* d_out, int out_size) {
    const float* X  = (const float*)d_in[0];
    const float* Wq = (const float*)d_in[1];
    const float* bq = (const float*)d_in[2];
    const float* Wk = (const float*)d_in[3];
    const float* bk = (const float*)d_in[4];
    const float* Wv = (const float*)d_in[5];
    const float* bv = (const float*)d_in[6];
    const float* Wi = (const float*)d_in[7];
    const float* bi = (const float*)d_in[8];
    const float* Wf = (const float*)d_in[9];
    const float* bf = (const float*)d_in[10];
    const float* Wo = (const float*)d_in[11];
    const float* bo = (const float*)d_in[12];
    float* out = (float*)d_out;

    const int LW = HH*HH;
    const int LB = HH;

    qkvg_kernel<<<BT/64, 256>>>(X, Wq, bq, Wk, bk, Wv, bv,
                                Wi + 0*LW, bi + 0*LB, Wf + 0*LW, bf + 0*LB);
    chunk_local_kernel<<<BB*NC, 256>>>();
    combine_kernel<<<BB*16, 256>>>();
    chunk_inter_kernel<<<BB*NC, 256>>>();
    hrec_kernel<<<BB, 256>>>(Wo + 0*LW, bo + 0*LB, nullptr);   // -> g_X1

    gates_kernel<<<BT/64, 256>>>(Wi + 1*LW, bi + 1*LB, Wf + 1*LW, bf + 1*LB);
    chunk_local_kernel<<<BB*NC, 256>>>();
    combine_kernel<<<BB*16, 256>>>();
    chunk_inter_kernel<<<BB*NC, 256>>>();
    hrec_kernel<<<BB, 256>>>(Wo + 1*LW, bo + 1*LB, out);
}

// round 12
// speedup vs baseline: 1.9948x; 1.1524x over previous
#include <cuda_runtime.h>
#include <cuda_bf16.h>
#include <cstddef>

#define BB   8
#define TT   1024
#define HH   128
#define BT   (BB*TT)
#define NC   32          // chunks per (batch,layer)
#define SS   32          // chunk size
#define LPAD 132         // smem row pitch (floats)

typedef unsigned long long ull;

// ---------------- device scratch ----------------
__device__ __align__(16) float g_Q [BT*HH];
__device__ __align__(16) float g_K [BT*HH];
__device__ __align__(16) float g_V [BT*HH];
__device__ __align__(16) float g_A [BT*HH];      // a = exp(zi) * v   (per layer)
__device__ __align__(16) float g_F [BT*HH];      // zf logits          (per layer)
__device__ __align__(16) float g_X1[BT*HH];      // layer-0 hidden output
__device__ __align__(16) float g_Attn[BT*HH];    // attn readout per layer
__device__ __align__(16) float g_Qt[BT*HH];      // q * exp(cum)
__device__ __align__(16) float g_E [BB*NC*HH];   // exp(cum_S) per (b,c,h)
__device__ __align__(16) float g_U [BB*NC*HH*HH];  // per-chunk At^T @ K
__device__ __align__(16) float g_Cb[BB*NC*HH*HH];  // C at chunk start

// ---------------- packed f32x2 helpers ----------------
__device__ __forceinline__ ull pk(float lo, float hi) {
    ull r; asm("mov.b64 %0,{%1,%2};" : "=l"(r) : "f"(lo), "f"(hi)); return r;
}
__device__ __forceinline__ void upk(ull v, float &lo, float &hi) {
    asm("mov.b64 {%0,%1},%2;" : "=f"(lo), "=f"(hi) : "l"(v));
}
__device__ __forceinline__ ull fma2(ull a, ull b, ull c) {
    ull d; asm("fma.rn.f32x2 %0,%1,%2,%3;" : "=l"(d) : "l"(a), "l"(b), "l"(c)); return d;
}
__device__ __forceinline__ ull add2(ull a, ull b) {
    ull d; asm("add.rn.f32x2 %0,%1,%2;" : "=l"(d) : "l"(a), "l"(b)); return d;
}

// ---------------- GEMM accumulation ----------------
__device__ __forceinline__ void gemm_acc(const float* xs, int rgp, int cg,
                                         const float* __restrict__ W,
                                         float acc[8][4]) {
    #pragma unroll
    for (int r = 0; r < 8; ++r) { acc[r][0]=0.f; acc[r][1]=0.f; acc[r][2]=0.f; acc[r][3]=0.f; }
    #pragma unroll 2
    for (int k4 = 0; k4 < 32; ++k4) {
        float4 xr[8];
        #pragma unroll
        for (int r = 0; r < 8; ++r)
            xr[r] = *(const float4*)&xs[(rgp*8 + r)*HH + k4*4];
        #pragma unroll
        for (int kk = 0; kk < 4; ++kk) {
            float4 w = *(const float4*)&W[(size_t)(k4*4 + kk)*HH + cg*4];
            #pragma unroll
            for (int r = 0; r < 8; ++r) {
                float xv = (kk==0) ? xr[r].x : (kk==1) ? xr[r].y : (kk==2) ? xr[r].z : xr[r].w;
                acc[r][0] = fmaf(xv, w.x, acc[r][0]);
                acc[r][1] = fmaf(xv, w.y, acc[r][1]);
                acc[r][2] = fmaf(xv, w.z, acc[r][2]);
                acc[r][3] = fmaf(xv, w.w, acc[r][3]);
            }
        }
    }
}

// MODE 0: identity -> global   MODE 2: exp * Vsrc -> global
template<int MODE>
__device__ __forceinline__ void gemm_pass(const float* xs, int row0, int rgp, int cg,
                                          const float* __restrict__ W,
                                          const float* __restrict__ bias,
                                          const float* __restrict__ Vsrc,
                                          float* __restrict__ Y) {
    float acc[8][4];
    gemm_acc(xs, rgp, cg, W, acc);
    float4 b4 = *(const float4*)&bias[cg*4];
    #pragma unroll
    for (int r = 0; r < 8; ++r) {
        size_t off = (size_t)(row0 + rgp*8 + r)*HH + cg*4;
        float4 o;
        o.x = acc[r][0] + b4.x; o.y = acc[r][1] + b4.y;
        o.z = acc[r][2] + b4.z; o.w = acc[r][3] + b4.w;
        if (MODE == 2) {
            o.x = __expf(o.x); o.y = __expf(o.y); o.z = __expf(o.z); o.w = __expf(o.w);
            float4 v = *(const float4*)&Vsrc[off];
            o.x *= v.x; o.y *= v.y; o.z *= v.z; o.w *= v.w;
        }
        *(float4*)&Y[off] = o;
    }
}

// ---------------- GEMM phase, split by pass: grid (128, 4) ----------------
// y=0: Q   y=1: K   y=2: V + A(=exp(zi)*v, v recomputed in-block)   y=3: F logits
__global__ __launch_bounds__(256) void mat_kernel(
    const float* __restrict__ X,
    const float* __restrict__ Wq, const float* __restrict__ bq,
    const float* __restrict__ Wk, const float* __restrict__ bk,
    const float* __restrict__ Wv, const float* __restrict__ bv,
    const float* __restrict__ Wi, const float* __restrict__ bi,
    const float* __restrict__ Wf, const float* __restrict__ bf) {
    __shared__ float xs[64*HH];
    const int tid = threadIdx.x;
    const int row0 = blockIdx.x * 64;
    for (int i = tid; i < 64*32; i += 256) {
        int r = i >> 5, c4 = i & 31;
        *(float4*)&xs[r*HH + c4*4] = *(const float4*)&X[(size_t)(row0 + r)*HH + c4*4];
    }
    __syncthreads();
    const int cg  = tid & 31;
    const int rgp = tid >> 5;
    const int y   = blockIdx.y;
    if (y == 0) {
        gemm_pass<0>(xs, row0, rgp, cg, Wq, bq, nullptr, g_Q);
    } else if (y == 1) {
        gemm_pass<0>(xs, row0, rgp, cg, Wk, bk, nullptr, g_K);
    } else if (y == 2) {
        float vacc[8][4];
        gemm_acc(xs, rgp, cg, Wv, vacc);
        float4 bv4 = *(const float4*)&bv[cg*4];
        #pragma unroll
        for (int r = 0; r < 8; ++r) {
            vacc[r][0] += bv4.x; vacc[r][1] += bv4.y;
            vacc[r][2] += bv4.z; vacc[r][3] += bv4.w;
            size_t off = (size_t)(row0 + rgp*8 + r)*HH + cg*4;
            *(float4*)&g_V[off] = make_float4(vacc[r][0], vacc[r][1], vacc[r][2], vacc[r][3]);
        }
        float iacc[8][4];
        gemm_acc(xs, rgp, cg, Wi, iacc);
        float4 bi4 = *(const float4*)&bi[cg*4];
        #pragma unroll
        for (int r = 0; r < 8; ++r) {
            size_t off = (size_t)(row0 + rgp*8 + r)*HH + cg*4;
            float4 o;
            o.x = __expf(iacc[r][0] + bi4.x) * vacc[r][0];
            o.y = __expf(iacc[r][1] + bi4.y) * vacc[r][1];
            o.z = __expf(iacc[r][2] + bi4.z) * vacc[r][2];
            o.w = __expf(iacc[r][3] + bi4.w) * vacc[r][3];
            *(float4*)&g_A[off] = o;
        }
    } else {
        gemm_pass<0>(xs, row0, rgp, cg, Wf, bf, nullptr, g_F);
    }
}

// Layer-1 gates from g_X1: grid (128, 2). y=0: A (reads stable g_V)  y=1: F logits
__global__ __launch_bounds__(256) void gates_kernel(
    const float* __restrict__ Wi, const float* __restrict__ bi,
    const float* __restrict__ Wf, const float* __restrict__ bf) {
    __shared__ float xs[64*HH];
    const int tid = threadIdx.x;
    const int row0 = blockIdx.x * 64;
    const float* X = (const float*)g_X1;
    for (int i = tid; i < 64*32; i += 256) {
        int r = i >> 5, c4 = i & 31;
        *(float4*)&xs[r*HH + c4*4] = *(const float4*)&X[(size_t)(row0 + r)*HH + c4*4];
    }
    __syncthreads();
    const int cg  = tid & 31;
    const int rgp = tid >> 5;
    if (blockIdx.y == 0)
        gemm_pass<2>(xs, row0, rgp, cg, Wi, bi, g_V, g_A);
    else
        gemm_pass<0>(xs, row0, rgp, cg, Wf, bf, nullptr, g_F);
}

// ---------------- chunk_local + fused cumsum: 256 CTAs ----------------
__global__ __launch_bounds__(256, 1) void chunk_local_kernel() {
    const int b = blockIdx.x >> 5, c = blockIdx.x & 31;
    const int tid = threadIdx.x;
    const size_t tb = ((size_t)b*TT + (size_t)c*SS) * HH;

    __shared__ float T1[SS][LPAD];
    __shared__ float T2[SS][LPAD];
    __shared__ float Gs[SS][SS+1];

    #pragma unroll
    for (int k = 0; k < 4; ++k) {
        int i = tid + k*256, s = i >> 5, c4 = i & 31;
        *(float4*)&T1[s][c4*4] = *(const float4*)&g_F[tb + (size_t)s*HH + c4*4];
        *(float4*)&T2[s][c4*4] = *(const float4*)&g_A[tb + (size_t)s*HH + c4*4];
    }
    __syncthreads();

    // cumsum along s for column h (tid<128)
    if (tid < 128) {
        const int h = tid;
        float cum = 0.f, e = 1.f;
        #pragma unroll 4
        for (int s = 0; s < SS; ++s) {
            cum += T1[s][h];
            e = __expf(cum);
            T1[s][h] = e;                       // e^{+cum}
            T2[s][h] *= __expf(-cum);           // At
        }
        g_E[(size_t)(b*NC + c)*HH + h] = e;
    }
    __syncthreads();

    // Qt = Q * e^{+cum} -> g_Qt
    #pragma unroll
    for (int k = 0; k < 4; ++k) {
        int i = tid + k*256, s = i >> 5, c4 = i & 31;
        float4 q = *(const float4*)&g_Q[tb + (size_t)s*HH + c4*4];
        float4 e4 = *(const float4*)&T1[s][c4*4];
        q.x *= e4.x; q.y *= e4.y; q.z *= e4.z; q.w *= e4.w;
        *(float4*)&g_Qt[tb + (size_t)s*HH + c4*4] = q;
    }
    __syncthreads();   // all T1(E) reads done

    // T1 <- K
    #pragma unroll
    for (int k = 0; k < 4; ++k) {
        int i = tid + k*256, s = i >> 5, c4 = i & 31;
        *(float4*)&T1[s][c4*4] = *(const float4*)&g_K[tb + (size_t)s*HH + c4*4];
    }
    __syncthreads();

    // U[h][j] = sum_s At[s][h] * K[s][j]
    {
        const int ty = tid >> 4, tx = tid & 15;
        const int h0 = ty*8, j0 = tx*8;
        float acc[8][8];
        #pragma unroll
        for (int r = 0; r < 8; ++r)
            #pragma unroll
            for (int q = 0; q < 8; ++q) acc[r][q] = 0.f;
        for (int s = 0; s < SS; ++s) {
            float av[8], kv[8];
            #pragma unroll
            for (int r = 0; r < 8; ++r) av[r] = T2[s][h0+r];
            #pragma unroll
            for (int q = 0; q < 8; ++q) kv[q] = T1[s][j0+q];
            #pragma unroll
            for (int r = 0; r < 8; ++r)
                #pragma unroll
                for (int q = 0; q < 8; ++q) acc[r][q] = fmaf(av[r], kv[q], acc[r][q]);
        }
        const size_t ub = (size_t)(b*NC + c) * (HH*HH);
        #pragma unroll
        for (int r = 0; r < 8; ++r) {
            *(float4*)&g_U[ub + (size_t)(h0+r)*HH + j0]     = make_float4(acc[r][0], acc[r][1], acc[r][2], acc[r][3]);
            *(float4*)&g_U[ub + (size_t)(h0+r)*HH + j0 + 4] = make_float4(acc[r][4], acc[r][5], acc[r][6], acc[r][7]);
        }
    }
    __syncthreads();

    // T1 <- Qt (same-CTA write, ordered by __syncthreads)
    #pragma unroll
    for (int k = 0; k < 4; ++k) {
        int i = tid + k*256, s = i >> 5, c4 = i & 31;
        *(float4*)&T1[s][c4*4] = *(const float4*)&g_Qt[tb + (size_t)s*HH + c4*4];
    }
    __syncthreads();

    // G[t][s] = sum_h Qt[t][h]*At[s][h], causal mask s<=t
    #pragma unroll
    for (int i2 = 0; i2 < 4; ++i2) {
        int e = tid*4 + i2, t = e >> 5, s = e & 31;
        float d0=0.f, d1=0.f, d2=0.f, d3=0.f;
        for (int h = 0; h < HH; h += 4) {
            d0 = fmaf(T1[t][h+0], T2[s][h+0], d0);
            d1 = fmaf(T1[t][h+1], T2[s][h+1], d1);
            d2 = fmaf(T1[t][h+2], T2[s][h+2], d2);
            d3 = fmaf(T1[t][h+3], T2[s][h+3], d3);
        }
        Gs[t][s] = (s <= t) ? ((d0+d1)+(d2+d3)) : 0.f;
    }
    __syncthreads();

    // T1 <- K (reload)
    #pragma unroll
    for (int k = 0; k < 4; ++k) {
        int i = tid + k*256, s = i >> 5, c4 = i & 31;
        *(float4*)&T1[s][c4*4] = *(const float4*)&g_K[tb + (size_t)s*HH + c4*4];
    }
    __syncthreads();

    // intra[t][j] = sum_s Gs[t][s]*K[s][j]
    {
        const int t = tid >> 3, j0 = (tid & 7) * 16;
        float acc[16];
        #pragma unroll
        for (int q = 0; q < 16; ++q) acc[q] = 0.f;
        for (int s = 0; s < SS; ++s) {
            float g = Gs[t][s];
            #pragma unroll
            for (int q = 0; q < 16; ++q) acc[q] = fmaf(g, T1[s][j0+q], acc[q]);
        }
        #pragma unroll
        for (int jj = 0; jj < 4; ++jj)
            *(float4*)&g_Attn[tb + (size_t)t*HH + j0 + jj*4] =
                make_float4(acc[jj*4], acc[jj*4+1], acc[jj*4+2], acc[jj*4+3]);
    }
}

// ---------------- chunk combine, 128 CTAs ----------------
__global__ __launch_bounds__(256, 1) void combine_kernel() {
    const int b  = blockIdx.x >> 4;
    const int hs = blockIdx.x & 15;
    const int tid = threadIdx.x;
    const int r  = hs*8 + (tid >> 5);
    const int c4 = tid & 31;

    const float4* U4 = (const float4*)g_U;
    float4* Cb4 = (float4*)g_Cb;
    const int elem = r*32 + c4;

    float4 C = make_float4(0.f, 0.f, 0.f, 0.f);
    size_t m0 = ((size_t)(b*NC) << 12) + elem;
    float4 u = __ldg(&U4[m0]);
    float  e = __ldg(&g_E[(size_t)(b*NC)*HH + r]);

    for (int c = 0; c < NC; ++c) {
        float4 un; float en;
        if (c + 1 < NC) {
            size_t mn = ((size_t)(b*NC + c + 1) << 12) + elem;
            un = __ldg(&U4[mn]);
            en = __ldg(&g_E[(size_t)(b*NC + c + 1)*HH + r]);
        } else { un = u; en = e; }
        Cb4[((size_t)(b*NC + c) << 12) + elem] = C;
        C.x = e*(C.x + u.x); C.y = e*(C.y + u.y);
        C.z = e*(C.z + u.z); C.w = e*(C.w + u.w);
        u = un; e = en;
    }
}

// ---------------- chunk_inter, register-tiled 4x4: attn += Qt @ Cb ----------------
__global__ __launch_bounds__(256, 1) void chunk_inter_kernel() {
    const int b = blockIdx.x >> 5, c = blockIdx.x & 31;
    const int tid = threadIdx.x;
    const size_t tb = ((size_t)b*TT + (size_t)c*SS) * HH;
    const size_t cb = (size_t)(b*NC + c) * (HH*HH);

    __shared__ float tQ[SS][LPAD];
    __shared__ float tC[32][LPAD];

    #pragma unroll
    for (int k = 0; k < 4; ++k) {
        int i = tid + k*256, s = i >> 5, c4 = i & 31;
        *(float4*)&tQ[s][c4*4] = *(const float4*)&g_Qt[tb + (size_t)s*HH + c4*4];
    }

    const int t0 = (tid >> 5) * 4;        // 4 t-rows
    const int j0 = (tid & 31) * 4;        // 4 j-cols
    float acc[4][4];
    #pragma unroll
    for (int r = 0; r < 4; ++r)
        #pragma unroll
        for (int q = 0; q < 4; ++q) acc[r][q] = 0.f;

    for (int hb = 0; hb < 4; ++hb) {
        __syncthreads();   // prior slab consumed; covers tQ load on first pass
        #pragma unroll
        for (int k = 0; k < 4; ++k) {
            int i = tid + k*256, s = i >> 5, c4 = i & 31;
            *(float4*)&tC[s][c4*4] = *(const float4*)&g_Cb[cb + (size_t)(hb*32 + s)*HH + c4*4];
        }
        __syncthreads();
        #pragma unroll 4
        for (int hh = 0; hh < 32; ++hh) {
            float4 cv = *(const float4*)&tC[hh][j0];
            float q0 = tQ[t0+0][hb*32 + hh];
            float q1 = tQ[t0+1][hb*32 + hh];
            float q2 = tQ[t0+2][hb*32 + hh];
            float q3 = tQ[t0+3][hb*32 + hh];
            acc[0][0] = fmaf(q0, cv.x, acc[0][0]); acc[0][1] = fmaf(q0, cv.y, acc[0][1]);
            acc[0][2] = fmaf(q0, cv.z, acc[0][2]); acc[0][3] = fmaf(q0, cv.w, acc[0][3]);
            acc[1][0] = fmaf(q1, cv.x, acc[1][0]); acc[1][1] = fmaf(q1, cv.y, acc[1][1]);
            acc[1][2] = fmaf(q1, cv.z, acc[1][2]); acc[1][3] = fmaf(q1, cv.w, acc[1][3]);
            acc[2][0] = fmaf(q2, cv.x, acc[2][0]); acc[2][1] = fmaf(q2, cv.y, acc[2][1]);
            acc[2][2] = fmaf(q2, cv.z, acc[2][2]); acc[2][3] = fmaf(q2, cv.w, acc[2][3]);
            acc[3][0] = fmaf(q3, cv.x, acc[3][0]); acc[3][1] = fmaf(q3, cv.y, acc[3][1]);
            acc[3][2] = fmaf(q3, cv.z, acc[3][2]); acc[3][3] = fmaf(q3, cv.w, acc[3][3]);
        }
    }

    #pragma unroll
    for (int r = 0; r < 4; ++r) {
        size_t off = tb + (size_t)(t0 + r)*HH + j0;
        float4 v = *(const float4*)&g_Attn[off];
        v.x += acc[r][0]; v.y += acc[r][1]; v.z += acc[r][2]; v.w += acc[r][3];
        *(float4*)&g_Attn[off] = v;
    }
}

// ---------------- h recurrence (unchanged; proven correct) ----------------
__global__ __launch_bounds__(256, 1) void hrec_kernel(
    const float* __restrict__ Wo, const float* __restrict__ bo,
    float* __restrict__ Xout_param) {
    const int b   = blockIdx.x;
    const int tid = threadIdx.x;
    const int j   = tid >> 1;
    const int hg  = tid & 1;
    const int i0  = hg * 64;
    const float NL2E = -1.44269504088896f;

    __shared__ __align__(16) float hbuf[2][HH];

    float* Xout = Xout_param ? Xout_param : g_X1;
    const size_t base = (size_t)b * TT * HH;
    const float* Attnb = g_Attn + base;

    ull w2[32];
    #pragma unroll
    for (int p = 0; p < 32; ++p)
        w2[p] = pk(NL2E * Wo[(size_t)(i0 + 2*p)*HH + j],
                   NL2E * Wo[(size_t)(i0 + 2*p + 1)*HH + j]);
    const float bo2 = NL2E * bo[j];

    if (tid < 128) hbuf[0][tid] = 0.f;

    float ring[8];
    #pragma unroll
    for (int u = 0; u < 8; ++u)
        ring[u] = __ldg(Attnb + (size_t)u*HH + j);

    for (int tb = 0; tb < TT; tb += 8) {
        #pragma unroll
        for (int u = 0; u < 8; ++u) {
            const int t = tb + u;
            __syncthreads();

            const ulonglong2* hb2 = (const ulonglong2*)hbuf[t & 1];
            ull s[8];
            #pragma unroll
            for (int q = 0; q < 8; ++q) s[q] = 0ull;
            #pragma unroll
            for (int q = 0; q < 16; ++q) {
                ulonglong2 hh = hb2[hg*16 + q];
                s[(2*q)   & 7] = fma2(hh.x, w2[2*q],     s[(2*q)   & 7]);
                s[(2*q+1) & 7] = fma2(hh.y, w2[2*q + 1], s[(2*q+1) & 7]);
            }
            ull t0 = add2(s[0], s[1]), t1 = add2(s[2], s[3]);
            ull t2 = add2(s[4], s[5]), t3 = add2(s[6], s[7]);
            ull st = add2(add2(t0, t1), add2(t2, t3));
            float lo, hi; upk(st, lo, hi);
            float zh = lo + hi;
            float zo = __shfl_xor_sync(0xffffffffu, zh, 1);
            float zl = zh + zo + bo2;
            float ex; asm("ex2.approx.f32 %0, %1;" : "=f"(ex) : "f"(zl));
            float den = 1.0f + ex;
            float o;  asm("rcp.approx.f32 %0, %1;" : "=f"(o) : "f"(den));
            float h = o * ring[u];
            hbuf[(t & 1) ^ 1][j] = h;
            Xout[base + (size_t)t*HH + j] = h;
            if (t + 8 < TT)
                ring[u] = __ldg(Attnb + (size_t)(t + 8)*HH + j);
        }
    }
}

// ---------------- launch ----------------
extern "C" void kernel_launch(void* const* d_in, const int* in_sizes, int n_in,
                              void* d_out, int out_size) {
    const float* X  = (const float*)d_in[0];
    const float* Wq = (const float*)d_in[1];
    const float* bq = (const float*)d_in[2];
    const float* Wk = (const float*)d_in[3];
    const float* bk = (const float*)d_in[4];
    const float* Wv = (const float*)d_in[5];
    const float* bv = (const float*)d_in[6];
    const float* Wi = (const float*)d_in[7];
    const float* bi = (const float*)d_in[8];
    const float* Wf = (const float*)d_in[9];
    const float* bf = (const float*)d_in[10];
    const float* Wo = (const float*)d_in[11];
    const float* bo = (const float*)d_in[12];
    float* out = (float*)d_out;

    const int LW = HH*HH;
    const int LB = HH;

    mat_kernel<<<dim3(BT/64, 4), 256>>>(X, Wq, bq, Wk, bk, Wv, bv,
                                        Wi + 0*LW, bi + 0*LB, Wf + 0*LW, bf + 0*LB);
    chunk_local_kernel<<<BB*NC, 256>>>();
    combine_kernel<<<BB*16, 256>>>();
    chunk_inter_kernel<<<BB*NC, 256>>>();
    hrec_kernel<<<BB, 256>>>(Wo + 0*LW, bo + 0*LB, nullptr);   // -> g_X1

    gates_kernel<<<dim3(BT/64, 2), 256>>>(Wi + 1*LW, bi + 1*LB, Wf + 1*LW, bf + 1*LB);
    chunk_local_kernel<<<BB*NC, 256>>>();
    combine_kernel<<<BB*16, 256>>>();
    chunk_inter_kernel<<<BB*NC, 256>>>();
    hrec_kernel<<<BB, 256>>>(Wo + 1*LW, bo + 1*LB, out);
}

// round 13
// speedup vs baseline: 2.6992x; 1.3531x over previous
#include <cuda_runtime.h>
#include <cuda_bf16.h>
#include <cstddef>

#define BB   8
#define TT   1024
#define HH   128
#define BT   (BB*TT)
#define NC   32          // chunks per (batch,layer)
#define SS   32          // chunk size
#define LPAD 132         // smem row pitch (floats)

typedef unsigned long long ull;

// ---------------- device scratch ----------------
__device__ __align__(16) float g_Q [BT*HH];
__device__ __align__(16) float g_K [BT*HH];
__device__ __align__(16) float g_V [BT*HH];
__device__ __align__(16) float g_A [BT*HH];      // a = exp(zi) * v   (per layer)
__device__ __align__(16) float g_F [BT*HH];      // zf logits          (per layer)
__device__ __align__(16) float g_X1[BT*HH];      // layer-0 hidden output
__device__ __align__(16) float g_Attn[BT*HH];    // attn readout per layer
__device__ __align__(16) float g_Qt[BT*HH];      // q * exp(cum)
__device__ __align__(16) float g_E [BB*NC*HH];   // exp(cum_S) per (b,c,h)
__device__ __align__(16) float g_U [BB*NC*HH*HH];  // per-chunk At^T @ K
__device__ __align__(16) float g_Cb[BB*NC*HH*HH];  // C at chunk start

// ---------------- packed f32x2 helpers ----------------
__device__ __forceinline__ ull pk(float lo, float hi) {
    ull r; asm("mov.b64 %0,{%1,%2};" : "=l"(r) : "f"(lo), "f"(hi)); return r;
}
__device__ __forceinline__ void upk(ull v, float &lo, float &hi) {
    asm("mov.b64 {%0,%1},%2;" : "=f"(lo), "=f"(hi) : "l"(v));
}
__device__ __forceinline__ ull fma2(ull a, ull b, ull c) {
    ull d; asm("fma.rn.f32x2 %0,%1,%2,%3;" : "=l"(d) : "l"(a), "l"(b), "l"(c)); return d;
}
__device__ __forceinline__ ull add2(ull a, ull b) {
    ull d; asm("add.rn.f32x2 %0,%1,%2;" : "=l"(d) : "l"(a), "l"(b)); return d;
}

// ---------------- GEMM accumulation ----------------
__device__ __forceinline__ void gemm_acc(const float* xs, int rgp, int cg,
                                         const float* __restrict__ W,
                                         float acc[8][4]) {
    #pragma unroll
    for (int r = 0; r < 8; ++r) { acc[r][0]=0.f; acc[r][1]=0.f; acc[r][2]=0.f; acc[r][3]=0.f; }
    #pragma unroll 2
    for (int k4 = 0; k4 < 32; ++k4) {
        float4 xr[8];
        #pragma unroll
        for (int r = 0; r < 8; ++r)
            xr[r] = *(const float4*)&xs[(rgp*8 + r)*HH + k4*4];
        #pragma unroll
        for (int kk = 0; kk < 4; ++kk) {
            float4 w = *(const float4*)&W[(size_t)(k4*4 + kk)*HH + cg*4];
            #pragma unroll
            for (int r = 0; r < 8; ++r) {
                float xv = (kk==0) ? xr[r].x : (kk==1) ? xr[r].y : (kk==2) ? xr[r].z : xr[r].w;
                acc[r][0] = fmaf(xv, w.x, acc[r][0]);
                acc[r][1] = fmaf(xv, w.y, acc[r][1]);
                acc[r][2] = fmaf(xv, w.z, acc[r][2]);
                acc[r][3] = fmaf(xv, w.w, acc[r][3]);
            }
        }
    }
}

// MODE 0: identity -> global   MODE 2: exp * Vsrc -> global
template<int MODE>
__device__ __forceinline__ void gemm_pass(const float* xs, int row0, int rgp, int cg,
                                          const float* __restrict__ W,
                                          const float* __restrict__ bias,
                                          const float* __restrict__ Vsrc,
                                          float* __restrict__ Y) {
    float acc[8][4];
    gemm_acc(xs, rgp, cg, W, acc);
    float4 b4 = *(const float4*)&bias[cg*4];
    #pragma unroll
    for (int r = 0; r < 8; ++r) {
        size_t off = (size_t)(row0 + rgp*8 + r)*HH + cg*4;
        float4 o;
        o.x = acc[r][0] + b4.x; o.y = acc[r][1] + b4.y;
        o.z = acc[r][2] + b4.z; o.w = acc[r][3] + b4.w;
        if (MODE == 2) {
            o.x = __expf(o.x); o.y = __expf(o.y); o.z = __expf(o.z); o.w = __expf(o.w);
            float4 v = *(const float4*)&Vsrc[off];
            o.x *= v.x; o.y *= v.y; o.z *= v.z; o.w *= v.w;
        }
        *(float4*)&Y[off] = o;
    }
}

// ---------------- GEMM phase, split by pass: grid (128, 4) ----------------
// y=0: Q   y=1: K   y=2: V + A(=exp(zi)*v, v recomputed in-block)   y=3: F logits
__global__ __launch_bounds__(256) void mat_kernel(
    const float* __restrict__ X,
    const float* __restrict__ Wq, const float* __restrict__ bq,
    const float* __restrict__ Wk, const float* __restrict__ bk,
    const float* __restrict__ Wv, const float* __restrict__ bv,
    const float* __restrict__ Wi, const float* __restrict__ bi,
    const float* __restrict__ Wf, const float* __restrict__ bf) {
    __shared__ float xs[64*HH];
    const int tid = threadIdx.x;
    const int row0 = blockIdx.x * 64;
    for (int i = tid; i < 64*32; i += 256) {
        int r = i >> 5, c4 = i & 31;
        *(float4*)&xs[r*HH + c4*4] = *(const float4*)&X[(size_t)(row0 + r)*HH + c4*4];
    }
    __syncthreads();
    const int cg  = tid & 31;
    const int rgp = tid >> 5;
    const int y   = blockIdx.y;
    if (y == 0) {
        gemm_pass<0>(xs, row0, rgp, cg, Wq, bq, nullptr, g_Q);
    } else if (y == 1) {
        gemm_pass<0>(xs, row0, rgp, cg, Wk, bk, nullptr, g_K);
    } else if (y == 2) {
        float vacc[8][4];
        gemm_acc(xs, rgp, cg, Wv, vacc);
        float4 bv4 = *(const float4*)&bv[cg*4];
        #pragma unroll
        for (int r = 0; r < 8; ++r) {
            vacc[r][0] += bv4.x; vacc[r][1] += bv4.y;
            vacc[r][2] += bv4.z; vacc[r][3] += bv4.w;
            size_t off = (size_t)(row0 + rgp*8 + r)*HH + cg*4;
            *(float4*)&g_V[off] = make_float4(vacc[r][0], vacc[r][1], vacc[r][2], vacc[r][3]);
        }
        float iacc[8][4];
        gemm_acc(xs, rgp, cg, Wi, iacc);
        float4 bi4 = *(const float4*)&bi[cg*4];
        #pragma unroll
        for (int r = 0; r < 8; ++r) {
            size_t off = (size_t)(row0 + rgp*8 + r)*HH + cg*4;
            float4 o;
            o.x = __expf(iacc[r][0] + bi4.x) * vacc[r][0];
            o.y = __expf(iacc[r][1] + bi4.y) * vacc[r][1];
            o.z = __expf(iacc[r][2] + bi4.z) * vacc[r][2];
            o.w = __expf(iacc[r][3] + bi4.w) * vacc[r][3];
            *(float4*)&g_A[off] = o;
        }
    } else {
        gemm_pass<0>(xs, row0, rgp, cg, Wf, bf, nullptr, g_F);
    }
}

// Layer-1 gates from g_X1: grid (128, 2). y=0: A (reads stable g_V)  y=1: F logits
__global__ __launch_bounds__(256) void gates_kernel(
    const float* __restrict__ Wi, const float* __restrict__ bi,
    const float* __restrict__ Wf, const float* __restrict__ bf) {
    __shared__ float xs[64*HH];
    const int tid = threadIdx.x;
    const int row0 = blockIdx.x * 64;
    const float* X = (const float*)g_X1;
    for (int i = tid; i < 64*32; i += 256) {
        int r = i >> 5, c4 = i & 31;
        *(float4*)&xs[r*HH + c4*4] = *(const float4*)&X[(size_t)(row0 + r)*HH + c4*4];
    }
    __syncthreads();
    const int cg  = tid & 31;
    const int rgp = tid >> 5;
    if (blockIdx.y == 0)
        gemm_pass<2>(xs, row0, rgp, cg, Wi, bi, g_V, g_A);
    else
        gemm_pass<0>(xs, row0, rgp, cg, Wf, bf, nullptr, g_F);
}

// ---------------- chunk_local + fused cumsum: 256 CTAs ----------------
__global__ __launch_bounds__(256, 1) void chunk_local_kernel() {
    const int b = blockIdx.x >> 5, c = blockIdx.x & 31;
    const int tid = threadIdx.x;
    const size_t tb = ((size_t)b*TT + (size_t)c*SS) * HH;

    __shared__ float T1[SS][LPAD];
    __shared__ float T2[SS][LPAD];
    __shared__ float Gs[SS][SS+1];

    #pragma unroll
    for (int k = 0; k < 4; ++k) {
        int i = tid + k*256, s = i >> 5, c4 = i & 31;
        *(float4*)&T1[s][c4*4] = *(const float4*)&g_F[tb + (size_t)s*HH + c4*4];
        *(float4*)&T2[s][c4*4] = *(const float4*)&g_A[tb + (size_t)s*HH + c4*4];
    }
    __syncthreads();

    // cumsum along s for column h (tid<128)
    if (tid < 128) {
        const int h = tid;
        float cum = 0.f, e = 1.f;
        #pragma unroll 4
        for (int s = 0; s < SS; ++s) {
            cum += T1[s][h];
            e = __expf(cum);
            T1[s][h] = e;                       // e^{+cum}
            T2[s][h] *= __expf(-cum);           // At
        }
        g_E[(size_t)(b*NC + c)*HH + h] = e;
    }
    __syncthreads();

    // Qt = Q * e^{+cum} -> g_Qt
    #pragma unroll
    for (int k = 0; k < 4; ++k) {
        int i = tid + k*256, s = i >> 5, c4 = i & 31;
        float4 q = *(const float4*)&g_Q[tb + (size_t)s*HH + c4*4];
        float4 e4 = *(const float4*)&T1[s][c4*4];
        q.x *= e4.x; q.y *= e4.y; q.z *= e4.z; q.w *= e4.w;
        *(float4*)&g_Qt[tb + (size_t)s*HH + c4*4] = q;
    }
    __syncthreads();   // all T1(E) reads done

    // T1 <- K
    #pragma unroll
    for (int k = 0; k < 4; ++k) {
        int i = tid + k*256, s = i >> 5, c4 = i & 31;
        *(float4*)&T1[s][c4*4] = *(const float4*)&g_K[tb + (size_t)s*HH + c4*4];
    }
    __syncthreads();

    // U[h][j] = sum_s At[s][h] * K[s][j]
    {
        const int ty = tid >> 4, tx = tid & 15;
        const int h0 = ty*8, j0 = tx*8;
        float acc[8][8];
        #pragma unroll
        for (int r = 0; r < 8; ++r)
            #pragma unroll
            for (int q = 0; q < 8; ++q) acc[r][q] = 0.f;
        for (int s = 0; s < SS; ++s) {
            float av[8], kv[8];
            #pragma unroll
            for (int r = 0; r < 8; ++r) av[r] = T2[s][h0+r];
            #pragma unroll
            for (int q = 0; q < 8; ++q) kv[q] = T1[s][j0+q];
            #pragma unroll
            for (int r = 0; r < 8; ++r)
                #pragma unroll
                for (int q = 0; q < 8; ++q) acc[r][q] = fmaf(av[r], kv[q], acc[r][q]);
        }
        const size_t ub = (size_t)(b*NC + c) * (HH*HH);
        #pragma unroll
        for (int r = 0; r < 8; ++r) {
            *(float4*)&g_U[ub + (size_t)(h0+r)*HH + j0]     = make_float4(acc[r][0], acc[r][1], acc[r][2], acc[r][3]);
            *(float4*)&g_U[ub + (size_t)(h0+r)*HH + j0 + 4] = make_float4(acc[r][4], acc[r][5], acc[r][6], acc[r][7]);
        }
    }
    __syncthreads();

    // T1 <- Qt (same-CTA write, ordered by __syncthreads)
    #pragma unroll
    for (int k = 0; k < 4; ++k) {
        int i = tid + k*256, s = i >> 5, c4 = i & 31;
        *(float4*)&T1[s][c4*4] = *(const float4*)&g_Qt[tb + (size_t)s*HH + c4*4];
    }
    __syncthreads();

    // G[t][s] = sum_h Qt[t][h]*At[s][h], causal mask s<=t
    #pragma unroll
    for (int i2 = 0; i2 < 4; ++i2) {
        int e = tid*4 + i2, t = e >> 5, s = e & 31;
        float d0=0.f, d1=0.f, d2=0.f, d3=0.f;
        for (int h = 0; h < HH; h += 4) {
            d0 = fmaf(T1[t][h+0], T2[s][h+0], d0);
            d1 = fmaf(T1[t][h+1], T2[s][h+1], d1);
            d2 = fmaf(T1[t][h+2], T2[s][h+2], d2);
            d3 = fmaf(T1[t][h+3], T2[s][h+3], d3);
        }
        Gs[t][s] = (s <= t) ? ((d0+d1)+(d2+d3)) : 0.f;
    }
    __syncthreads();

    // T1 <- K (reload)
    #pragma unroll
    for (int k = 0; k < 4; ++k) {
        int i = tid + k*256, s = i >> 5, c4 = i & 31;
        *(float4*)&T1[s][c4*4] = *(const float4*)&g_K[tb + (size_t)s*HH + c4*4];
    }
    __syncthreads();

    // intra[t][j] = sum_s Gs[t][s]*K[s][j]
    {
        const int t = tid >> 3, j0 = (tid & 7) * 16;
        float acc[16];
        #pragma unroll
        for (int q = 0; q < 16; ++q) acc[q] = 0.f;
        for (int s = 0; s < SS; ++s) {
            float g = Gs[t][s];
            #pragma unroll
            for (int q = 0; q < 16; ++q) acc[q] = fmaf(g, T1[s][j0+q], acc[q]);
        }
        #pragma unroll
        for (int jj = 0; jj < 4; ++jj)
            *(float4*)&g_Attn[tb + (size_t)t*HH + j0 + jj*4] =
                make_float4(acc[jj*4], acc[jj*4+1], acc[jj*4+2], acc[jj*4+3]);
    }
}

// ---------------- chunk combine, 128 CTAs ----------------
__global__ __launch_bounds__(256, 1) void combine_kernel() {
    const int b  = blockIdx.x >> 4;
    const int hs = blockIdx.x & 15;
    const int tid = threadIdx.x;
    const int r  = hs*8 + (tid >> 5);
    const int c4 = tid & 31;

    const float4* U4 = (const float4*)g_U;
    float4* Cb4 = (float4*)g_Cb;
    const int elem = r*32 + c4;

    float4 C = make_float4(0.f, 0.f, 0.f, 0.f);
    size_t m0 = ((size_t)(b*NC) << 12) + elem;
    float4 u = __ldg(&U4[m0]);
    float  e = __ldg(&g_E[(size_t)(b*NC)*HH + r]);

    for (int c = 0; c < NC; ++c) {
        float4 un; float en;
        if (c + 1 < NC) {
            size_t mn = ((size_t)(b*NC + c + 1) << 12) + elem;
            un = __ldg(&U4[mn]);
            en = __ldg(&g_E[(size_t)(b*NC + c + 1)*HH + r]);
        } else { un = u; en = e; }
        Cb4[((size_t)(b*NC + c) << 12) + elem] = C;
        C.x = e*(C.x + u.x); C.y = e*(C.y + u.y);
        C.z = e*(C.z + u.z); C.w = e*(C.w + u.w);
        u = un; e = en;
    }
}

// ---------------- chunk_inter, register-tiled 4x4: attn += Qt @ Cb ----------------
__global__ __launch_bounds__(256, 1) void chunk_inter_kernel() {
    const int b = blockIdx.x >> 5, c = blockIdx.x & 31;
    const int tid = threadIdx.x;
    const size_t tb = ((size_t)b*TT + (size_t)c*SS) * HH;
    const size_t cb = (size_t)(b*NC + c) * (HH*HH);

    __shared__ float tQ[SS][LPAD];
    __shared__ float tC[32][LPAD];

    #pragma unroll
    for (int k = 0; k < 4; ++k) {
        int i = tid + k*256, s = i >> 5, c4 = i & 31;
        *(float4*)&tQ[s][c4*4] = *(const float4*)&g_Qt[tb + (size_t)s*HH + c4*4];
    }

    const int t0 = (tid >> 5) * 4;        // 4 t-rows
    const int j0 = (tid & 31) * 4;        // 4 j-cols
    float acc[4][4];
    #pragma unroll
    for (int r = 0; r < 4; ++r)
        #pragma unroll
        for (int q = 0; q < 4; ++q) acc[r][q] = 0.f;

    for (int hb = 0; hb < 4; ++hb) {
        __syncthreads();   // prior slab consumed; covers tQ load on first pass
        #pragma unroll
        for (int k = 0; k < 4; ++k) {
            int i = tid + k*256, s = i >> 5, c4 = i & 31;
            *(float4*)&tC[s][c4*4] = *(const float4*)&g_Cb[cb + (size_t)(hb*32 + s)*HH + c4*4];
        }
        __syncthreads();
        #pragma unroll 4
        for (int hh = 0; hh < 32; ++hh) {
            float4 cv = *(const float4*)&tC[hh][j0];
            float q0 = tQ[t0+0][hb*32 + hh];
            float q1 = tQ[t0+1][hb*32 + hh];
            float q2 = tQ[t0+2][hb*32 + hh];
            float q3 = tQ[t0+3][hb*32 + hh];
            acc[0][0] = fmaf(q0, cv.x, acc[0][0]); acc[0][1] = fmaf(q0, cv.y, acc[0][1]);
            acc[0][2] = fmaf(q0, cv.z, acc[0][2]); acc[0][3] = fmaf(q0, cv.w, acc[0][3]);
            acc[1][0] = fmaf(q1, cv.x, acc[1][0]); acc[1][1] = fmaf(q1, cv.y, acc[1][1]);
            acc[1][2] = fmaf(q1, cv.z, acc[1][2]); acc[1][3] = fmaf(q1, cv.w, acc[1][3]);
            acc[2][0] = fmaf(q2, cv.x, acc[2][0]); acc[2][1] = fmaf(q2, cv.y, acc[2][1]);
            acc[2][2] = fmaf(q2, cv.z, acc[2][2]); acc[2][3] = fmaf(q2, cv.w, acc[2][3]);
            acc[3][0] = fmaf(q3, cv.x, acc[3][0]); acc[3][1] = fmaf(q3, cv.y, acc[3][1]);
            acc[3][2] = fmaf(q3, cv.z, acc[3][2]); acc[3][3] = fmaf(q3, cv.w, acc[3][3]);
        }
    }

    #pragma unroll
    for (int r = 0; r < 4; ++r) {
        size_t off = tb + (size_t)(t0 + r)*HH + j0;
        float4 v = *(const float4*)&g_Attn[off];
        v.x += acc[r][0]; v.y += acc[r][1]; v.z += acc[r][2]; v.w += acc[r][3];
        *(float4*)&g_Attn[off] = v;
    }
}

// ---------------- h recurrence: 128 threads, ONE FULL COLUMN PER THREAD ----------------
// Thread j owns Wo[:,j] as 64 packed f32x2 registers. Per step: 32 broadcast
// LDS.128 of h + 64 independent fma2 over 8 accumulator chains (exactly the
// per-SM fp32 issue floor), no shfl, sigma once, 1 warp per SMSP.
__global__ __launch_bounds__(128, 1) void hrec_kernel(
    const float* __restrict__ Wo, const float* __restrict__ bo,
    float* __restrict__ Xout_param) {
    const int b = blockIdx.x;
    const int j = threadIdx.x;            // 0..127 column
    const float NL2E = -1.44269504088896f;

    __shared__ __align__(16) float hbuf[2][HH];

    float* Xout = Xout_param ? Xout_param : g_X1;
    const size_t base = (size_t)b * TT * HH;
    const float* Attnb = g_Attn + base;

    // full Wo column, pre-scaled by -log2(e), packed over i pairs
    ull w2[64];
    #pragma unroll
    for (int p = 0; p < 64; ++p)
        w2[p] = pk(NL2E * Wo[(size_t)(2*p)*HH + j],
                   NL2E * Wo[(size_t)(2*p + 1)*HH + j]);
    const float bo2 = NL2E * bo[j];

    hbuf[0][j] = 0.f;

    float ring[8];
    #pragma unroll
    for (int u = 0; u < 8; ++u)
        ring[u] = __ldg(Attnb + (size_t)u*HH + j);

    for (int tb = 0; tb < TT; tb += 8) {
        #pragma unroll
        for (int u = 0; u < 8; ++u) {
            const int t = tb + u;
            __syncthreads();   // hbuf[t&1] (written at t-1) visible to all

            const ulonglong2* hb2 = (const ulonglong2*)hbuf[t & 1];
            ull s[8];
            #pragma unroll
            for (int q = 0; q < 8; ++q) s[q] = 0ull;
            #pragma unroll
            for (int k = 0; k < 32; ++k) {
                ulonglong2 hh = hb2[k];          // h[4k..4k+3], broadcast across warp
                s[(2*k)   & 7] = fma2(hh.x, w2[2*k],     s[(2*k)   & 7]);
                s[(2*k+1) & 7] = fma2(hh.y, w2[2*k + 1], s[(2*k+1) & 7]);
            }
            ull t0 = add2(s[0], s[1]), t1 = add2(s[2], s[3]);
            ull t2 = add2(s[4], s[5]), t3 = add2(s[6], s[7]);
            ull st = add2(add2(t0, t1), add2(t2, t3));
            float lo, hi; upk(st, lo, hi);
            float zl = lo + hi + bo2;            // = -z * log2(e)
            float ex; asm("ex2.approx.f32 %0, %1;" : "=f"(ex) : "f"(zl));   // e^-z
            float den = 1.0f + ex;
            float o;  asm("rcp.approx.f32 %0, %1;" : "=f"(o) : "f"(den));
            float h = o * ring[u];
            hbuf[(t & 1) ^ 1][j] = h;
            Xout[base + (size_t)t*HH + j] = h;
            if (t + 8 < TT)
                ring[u] = __ldg(Attnb + (size_t)(t + 8)*HH + j);
        }
    }
}

// ---------------- launch ----------------
extern "C" void kernel_launch(void* const* d_in, const int* in_sizes, int n_in,
                              void* d_out, int out_size) {
    const float* X  = (const float*)d_in[0];
    const float* Wq = (const float*)d_in[1];
    const float* bq = (const float*)d_in[2];
    const float* Wk = (const float*)d_in[3];
    const float* bk = (const float*)d_in[4];
    const float* Wv = (const float*)d_in[5];
    const float* bv = (const float*)d_in[6];
    const float* Wi = (const float*)d_in[7];
    const float* bi = (const float*)d_in[8];
    const float* Wf = (const float*)d_in[9];
    const float* bf = (const float*)d_in[10];
    const float* Wo = (const float*)d_in[11];
    const float* bo = (const float*)d_in[12];
    float* out = (float*)d_out;

    const int LW = HH*HH;
    const int LB = HH;

    mat_kernel<<<dim3(BT/64, 4), 256>>>(X, Wq, bq, Wk, bk, Wv, bv,
                                        Wi + 0*LW, bi + 0*LB, Wf + 0*LW, bf + 0*LB);
    chunk_local_kernel<<<BB*NC, 256>>>();
    combine_kernel<<<BB*16, 256>>>();
    chunk_inter_kernel<<<BB*NC, 256>>>();
    hrec_kernel<<<BB, 128>>>(Wo + 0*LW, bo + 0*LB, nullptr);   // -> g_X1

    gates_kernel<<<dim3(BT/64, 2), 256>>>(Wi + 1*LW, bi + 1*LB, Wf + 1*LW, bf + 1*LB);
    chunk_local_kernel<<<BB*NC, 256>>>();
    combine_kernel<<<BB*16, 256>>>();
    chunk_inter_kernel<<<BB*NC, 256>>>();
    hrec_kernel<<<BB, 128>>>(Wo + 1*LW, bo + 1*LB, out);
}